// round 3
// baseline (speedup 1.0000x reference)
#include <cuda_runtime.h>
#include <math.h>

#define D_  768
#define H_  12
#define HD_ 64
#define FF_ 3072
#define B_  8
#define N_  1024
#define M_  (B_*N_)          // 8192 rows
#define SCALING_ 0.125f      // HD^-0.5
#define EPS_ 1e-5f

// ---------------- scratch (static device globals; no allocation) -------------
__device__ float g_h  [M_*D_];   // LN1 out, reused as LN2 out
__device__ float g_q  [M_*D_];
__device__ float g_k  [M_*D_];
__device__ float g_v  [M_*D_];
__device__ float g_att[M_*D_];
__device__ float g_ff [M_*FF_];

// ---------------- LayerNorm: one block per row -------------------------------
__global__ __launch_bounds__(256)
void ln_kernel(const float* __restrict__ x, const float* __restrict__ w,
               const float* __restrict__ b, float* __restrict__ out) {
    const int row = blockIdx.x;
    const int tid = threadIdx.x;
    const float* xr = x + (size_t)row * D_;
    float v[3];
    float s = 0.f;
    #pragma unroll
    for (int i = 0; i < 3; i++) { v[i] = xr[tid + i*256]; s += v[i]; }

    __shared__ float red[8];
    __shared__ float bc[2];
    #pragma unroll
    for (int o = 16; o; o >>= 1) s += __shfl_xor_sync(0xffffffffu, s, o);
    if ((tid & 31) == 0) red[tid >> 5] = s;
    __syncthreads();
    if (tid == 0) {
        float t = 0.f;
        #pragma unroll
        for (int i = 0; i < 8; i++) t += red[i];
        bc[0] = t * (1.0f / D_);
    }
    __syncthreads();
    const float mu = bc[0];

    float s2 = 0.f;
    #pragma unroll
    for (int i = 0; i < 3; i++) { float d = v[i] - mu; s2 += d * d; }
    #pragma unroll
    for (int o = 16; o; o >>= 1) s2 += __shfl_xor_sync(0xffffffffu, s2, o);
    if ((tid & 31) == 0) red[tid >> 5] = s2;
    __syncthreads();
    if (tid == 0) {
        float t = 0.f;
        #pragma unroll
        for (int i = 0; i < 8; i++) t += red[i];
        bc[1] = rsqrtf(t * (1.0f / D_) + EPS_);
    }
    __syncthreads();
    const float rstd = bc[1];

    float* orow = out + (size_t)row * D_;
    #pragma unroll
    for (int i = 0; i < 3; i++) {
        int c = tid + i*256;
        orow[c] = (v[i] - mu) * rstd * w[c] + b[c];
    }
}

// ---------------- tf32 helpers -----------------------------------------------
__device__ __forceinline__ unsigned f2tf32(float f) {
    unsigned r;
    asm("cvt.rna.tf32.f32 %0, %1;" : "=r"(r) : "f"(f));
    return r;
}

__device__ __forceinline__ void mma_tf32(float& c0, float& c1, float& c2, float& c3,
                                         unsigned a0, unsigned a1, unsigned a2, unsigned a3,
                                         unsigned b0, unsigned b1) {
    asm volatile(
        "mma.sync.aligned.m16n8k8.row.col.f32.tf32.tf32.f32 "
        "{%0,%1,%2,%3}, {%4,%5,%6,%7}, {%8,%9}, {%0,%1,%2,%3};"
        : "+f"(c0), "+f"(c1), "+f"(c2), "+f"(c3)
        : "r"(a0), "r"(a1), "r"(a2), "r"(a3), "r"(b0), "r"(b1));
}

// ---------------- tf32 NT GEMM: C[M,N] = A[M,K] @ W[N,K]^T + bias ------------
// 128x128 CTA tile, 8 warps (2x4), warp tile 64x32, k-step 16, double buffered.
// Smem uses a K-permuted layout so fragment reads are single LDS.128:
//   slot(k) = (k&3)*4 + ((k>>2)&1) + (k>=8 ? 2 : 0)
// A thread (grp,qk) then finds {k8=0:qk, qk+4, k8=8:qk, qk+4} at words qk*4..qk*4+3.
// EP: 0 = plain, 1 = *SCALING, 2 = exact GELU, 3 = + res[r,c]
template<int EP>
__global__ __launch_bounds__(256, 1)
void gemm_tf32(const float* __restrict__ A, const float* __restrict__ W,
               const float* __restrict__ bias, const float* __restrict__ res,
               float* __restrict__ C, int M, int N, int K) {
    __shared__ unsigned As[2][128][16];
    __shared__ unsigned Ws[2][128][16];

    const int tid  = threadIdx.x;
    const int lane = tid & 31;
    const int warp = tid >> 5;
    const int wm = (warp >> 2) * 64;   // 0 or 64
    const int wn = (warp & 3) * 32;    // 0,32,64,96
    const int grp = lane >> 2;         // 0..7
    const int qk  = lane & 3;          // 0..3

    const int m0 = blockIdx.y << 7, n0 = blockIdx.x << 7;

    // producer mapping: row = tid>>2 (and +64), k-chunk = (tid&3)*4
    const int ldr = tid >> 2;
    const int sub = tid & 3;           // which k-quad
    const float* Ap0 = A + (size_t)(m0 + ldr) * K + (sub << 2);
    const float* Ap1 = A + (size_t)(m0 + ldr + 64) * K + (sub << 2);
    const float* Wp0 = W + (size_t)(n0 + ldr) * K + (sub << 2);
    const float* Wp1 = W + (size_t)(n0 + ldr + 64) * K + (sub << 2);

    float acc[4][4][4];   // [mi][ni][frag]
    #pragma unroll
    for (int i = 0; i < 4; i++)
        #pragma unroll
        for (int j = 0; j < 4; j++)
            #pragma unroll
            for (int f = 0; f < 4; f++) acc[i][j][f] = 0.f;

    const int ntiles = K >> 4;

    // store slot for element i of the float4: i*4 + sub
    #define STORE_TILE(buf, a0v, a1v, w0v, w1v)                                   \
        do {                                                                       \
            As[buf][ldr   ][0*4+sub]=f2tf32(a0v.x); As[buf][ldr   ][1*4+sub]=f2tf32(a0v.y); \
            As[buf][ldr   ][2*4+sub]=f2tf32(a0v.z); As[buf][ldr   ][3*4+sub]=f2tf32(a0v.w); \
            As[buf][ldr+64][0*4+sub]=f2tf32(a1v.x); As[buf][ldr+64][1*4+sub]=f2tf32(a1v.y); \
            As[buf][ldr+64][2*4+sub]=f2tf32(a1v.z); As[buf][ldr+64][3*4+sub]=f2tf32(a1v.w); \
            Ws[buf][ldr   ][0*4+sub]=f2tf32(w0v.x); Ws[buf][ldr   ][1*4+sub]=f2tf32(w0v.y); \
            Ws[buf][ldr   ][2*4+sub]=f2tf32(w0v.z); Ws[buf][ldr   ][3*4+sub]=f2tf32(w0v.w); \
            Ws[buf][ldr+64][0*4+sub]=f2tf32(w1v.x); Ws[buf][ldr+64][1*4+sub]=f2tf32(w1v.y); \
            Ws[buf][ldr+64][2*4+sub]=f2tf32(w1v.z); Ws[buf][ldr+64][3*4+sub]=f2tf32(w1v.w); \
        } while (0)

    // NOTE on slot math: global k for element i is sub*4 + i, whose slot is
    // ((sub*4+i)&3)*4 + (((sub*4+i)>>2)&1) + ((sub*4+i)>=8?2:0) = i*4 + sub. Exactly above.

    // prologue
    {
        float4 a0 = *(const float4*)(Ap0);
        float4 a1 = *(const float4*)(Ap1);
        float4 w0 = *(const float4*)(Wp0);
        float4 w1 = *(const float4*)(Wp1);
        STORE_TILE(0, a0, a1, w0, w1);
    }
    __syncthreads();

    for (int it = 0; it < ntiles; it++) {
        const int cur = it & 1, nxt = cur ^ 1;
        float4 a0, a1, w0, w1;
        const bool have_next = (it + 1) < ntiles;
        if (have_next) {
            const int ko = (it + 1) << 4;
            a0 = *(const float4*)(Ap0 + ko);
            a1 = *(const float4*)(Ap1 + ko);
            w0 = *(const float4*)(Wp0 + ko);
            w1 = *(const float4*)(Wp1 + ko);
        }

        // one LDS.128 per fragment group: covers BOTH k8 steps
        uint4 Alo[4], Ahi[4], Bv[4];
        #pragma unroll
        for (int mi = 0; mi < 4; mi++) {
            const int m = wm + (mi << 4);
            Alo[mi] = *(const uint4*)&As[cur][m + grp    ][qk << 2];
            Ahi[mi] = *(const uint4*)&As[cur][m + grp + 8][qk << 2];
        }
        #pragma unroll
        for (int ni = 0; ni < 4; ni++) {
            const int n = wn + (ni << 3);
            Bv[ni] = *(const uint4*)&Ws[cur][n + grp][qk << 2];
        }

        // ks = 0: fragments (.x = k8+qk, .y = k8+qk+4)
        #pragma unroll
        for (int mi = 0; mi < 4; mi++)
            #pragma unroll
            for (int ni = 0; ni < 4; ni++)
                mma_tf32(acc[mi][ni][0], acc[mi][ni][1], acc[mi][ni][2], acc[mi][ni][3],
                         Alo[mi].x, Ahi[mi].x, Alo[mi].y, Ahi[mi].y,
                         Bv[ni].x, Bv[ni].y);
        // ks = 1: (.z, .w)
        #pragma unroll
        for (int mi = 0; mi < 4; mi++)
            #pragma unroll
            for (int ni = 0; ni < 4; ni++)
                mma_tf32(acc[mi][ni][0], acc[mi][ni][1], acc[mi][ni][2], acc[mi][ni][3],
                         Alo[mi].z, Ahi[mi].z, Alo[mi].w, Ahi[mi].w,
                         Bv[ni].z, Bv[ni].w);

        if (have_next) {
            STORE_TILE(nxt, a0, a1, w0, w1);
        }
        __syncthreads();
    }
    #undef STORE_TILE

    // epilogue
    #pragma unroll
    for (int mi = 0; mi < 4; mi++) {
        #pragma unroll
        for (int ni = 0; ni < 4; ni++) {
            #pragma unroll
            for (int f = 0; f < 4; f++) {
                const int r = m0 + wm + (mi << 4) + grp + ((f >> 1) << 3);
                const int c = n0 + wn + (ni << 3) + (qk << 1) + (f & 1);
                float val = acc[mi][ni][f] + bias[c];
                if (EP == 1) val *= SCALING_;
                if (EP == 2) val = 0.5f * val * (1.0f + erff(val * 0.70710678118654752f));
                if (EP == 3) val += res[(size_t)r * N + c];
                C[(size_t)r * N + c] = val;
            }
        }
    }
}

// ---------------- RoPE (interleaved pairs), in-place -------------------------
__global__ void rope_kernel(float* __restrict__ t, const float* __restrict__ freqs, int npairs) {
    int idx = blockIdx.x * blockDim.x + threadIdx.x;
    if (idx >= npairs) return;
    const int row = idx / (D_ / 2);
    const int p   = idx - row * (D_ / 2);
    const int i   = p & 31;
    const int n   = row & (N_ - 1);
    const float ang = (float)n * freqs[i];
    const float c = cosf(ang), s = sinf(ang);
    float* base = t + (size_t)row * D_ + p * 2;
    const float x0 = base[0], x1 = base[1];
    base[0] = x0 * c - x1 * s;
    base[1] = x1 * c + x0 * s;
}

// ---------------- flash attention, fp32, BQ=64 BK=32 -------------------------
__device__ __forceinline__ float rmax16(float v) {
    #pragma unroll
    for (int o = 8; o; o >>= 1) v = fmaxf(v, __shfl_xor_sync(0xffffffffu, v, o, 16));
    return v;
}
__device__ __forceinline__ float rsum16(float v) {
    #pragma unroll
    for (int o = 8; o; o >>= 1) v += __shfl_xor_sync(0xffffffffu, v, o, 16);
    return v;
}

__global__ __launch_bounds__(256)
void attn_kernel(const float* __restrict__ q, const float* __restrict__ k,
                 const float* __restrict__ v, const unsigned char* __restrict__ pm,
                 float* __restrict__ out) {
    __shared__ float Qs[64][65];
    __shared__ float Ks[64][33];
    __shared__ float Vs[32][68];
    __shared__ float Ps[64][33];
    __shared__ unsigned char Ms[32];

    const int tid = threadIdx.x;
    const int tx = tid & 15, ty = tid >> 4;
    const int qt = blockIdx.x, bh = blockIdx.y;
    const int b = bh / H_, h = bh - b * H_;
    const int row0 = b * N_ + qt * 64;
    const int colh = h * HD_;

    for (int idx = tid; idx < 64 * 64; idx += 256) {
        const int r = idx >> 6, d = idx & 63;
        Qs[d][r] = q[(size_t)(row0 + r) * D_ + colh + d];
    }

    float o[4][4];
    #pragma unroll
    for (int i = 0; i < 4; i++)
        #pragma unroll
        for (int j = 0; j < 4; j++) o[i][j] = 0.f;
    float mreg[4], lreg[4];
    #pragma unroll
    for (int i = 0; i < 4; i++) { mreg[i] = -3.0e38f; lreg[i] = 0.f; }

    const int r0  = ty << 2;
    const int c0s = tx << 1;
    const int c0o = tx << 2;

    for (int kt = 0; kt < N_; kt += 32) {
        for (int idx = tid; idx < 32 * 64; idx += 256) {
            const int c = idx >> 6, d = idx & 63;
            const size_t g = (size_t)(b * N_ + kt + c) * D_ + colh + d;
            Ks[d][c] = k[g];
            Vs[c][d] = v[g];
        }
        if (tid < 32) Ms[tid] = pm[b * N_ + kt + tid];
        __syncthreads();

        float s[4][2];
        s[0][0]=s[0][1]=s[1][0]=s[1][1]=s[2][0]=s[2][1]=s[3][0]=s[3][1]=0.f;
        #pragma unroll 4
        for (int d = 0; d < 64; d++) {
            const float a0 = Qs[d][r0], a1 = Qs[d][r0+1], a2 = Qs[d][r0+2], a3 = Qs[d][r0+3];
            const float b0 = Ks[d][c0s], b1 = Ks[d][c0s+1];
            s[0][0] = fmaf(a0, b0, s[0][0]); s[0][1] = fmaf(a0, b1, s[0][1]);
            s[1][0] = fmaf(a1, b0, s[1][0]); s[1][1] = fmaf(a1, b1, s[1][1]);
            s[2][0] = fmaf(a2, b0, s[2][0]); s[2][1] = fmaf(a2, b1, s[2][1]);
            s[3][0] = fmaf(a3, b0, s[3][0]); s[3][1] = fmaf(a3, b1, s[3][1]);
        }
        const bool msk0 = Ms[c0s] != 0, msk1 = Ms[c0s+1] != 0;
        #pragma unroll
        for (int i = 0; i < 4; i++) {
            s[i][0] = msk0 ? -3.0e38f : s[i][0] * 0.125f;
            s[i][1] = msk1 ? -3.0e38f : s[i][1] * 0.125f;
        }

        #pragma unroll
        for (int i = 0; i < 4; i++) {
            float mt = rmax16(fmaxf(s[i][0], s[i][1]));
            const float mnew = fmaxf(mreg[i], mt);
            const float alpha = __expf(mreg[i] - mnew);
            const float p0 = __expf(s[i][0] - mnew);
            const float p1 = __expf(s[i][1] - mnew);
            const float rs = rsum16(p0 + p1);
            lreg[i] = lreg[i] * alpha + rs;
            mreg[i] = mnew;
            #pragma unroll
            for (int j = 0; j < 4; j++) o[i][j] *= alpha;
            Ps[r0 + i][c0s]     = p0;
            Ps[r0 + i][c0s + 1] = p1;
        }
        __syncthreads();

        #pragma unroll 4
        for (int kk = 0; kk < 32; kk++) {
            const float4 vv = *(const float4*)&Vs[kk][c0o];
            const float p0 = Ps[r0][kk],   p1 = Ps[r0+1][kk];
            const float p2 = Ps[r0+2][kk], p3 = Ps[r0+3][kk];
            o[0][0] = fmaf(p0, vv.x, o[0][0]); o[0][1] = fmaf(p0, vv.y, o[0][1]);
            o[0][2] = fmaf(p0, vv.z, o[0][2]); o[0][3] = fmaf(p0, vv.w, o[0][3]);
            o[1][0] = fmaf(p1, vv.x, o[1][0]); o[1][1] = fmaf(p1, vv.y, o[1][1]);
            o[1][2] = fmaf(p1, vv.z, o[1][2]); o[1][3] = fmaf(p1, vv.w, o[1][3]);
            o[2][0] = fmaf(p2, vv.x, o[2][0]); o[2][1] = fmaf(p2, vv.y, o[2][1]);
            o[2][2] = fmaf(p2, vv.z, o[2][2]); o[2][3] = fmaf(p2, vv.w, o[2][3]);
            o[3][0] = fmaf(p3, vv.x, o[3][0]); o[3][1] = fmaf(p3, vv.y, o[3][1]);
            o[3][2] = fmaf(p3, vv.z, o[3][2]); o[3][3] = fmaf(p3, vv.w, o[3][3]);
        }
        __syncthreads();
    }

    #pragma unroll
    for (int i = 0; i < 4; i++) {
        const float inv = 1.0f / lreg[i];
        float4 r4;
        r4.x = o[i][0] * inv; r4.y = o[i][1] * inv;
        r4.z = o[i][2] * inv; r4.w = o[i][3] * inv;
        *(float4*)&out[(size_t)(row0 + r0 + i) * D_ + colh + c0o] = r4;
    }
}

// ---------------- launch ------------------------------------------------------
extern "C" void kernel_launch(void* const* d_in, const int* in_sizes, int n_in,
                              void* d_out, int out_size) {
    const float* x     = (const float*)d_in[0];
    const unsigned char* pmask = (const unsigned char*)d_in[1];
    const float* wq = (const float*)d_in[2];
    const float* bq = (const float*)d_in[3];
    const float* wk = (const float*)d_in[4];
    const float* bk = (const float*)d_in[5];
    const float* wv = (const float*)d_in[6];
    const float* bv = (const float*)d_in[7];
    const float* wo = (const float*)d_in[8];
    const float* bo = (const float*)d_in[9];
    const float* w1 = (const float*)d_in[10];
    const float* b1 = (const float*)d_in[11];
    const float* w2 = (const float*)d_in[12];
    const float* b2 = (const float*)d_in[13];
    const float* ln1w = (const float*)d_in[14];
    const float* ln1b = (const float*)d_in[15];
    const float* ln2w = (const float*)d_in[16];
    const float* ln2b = (const float*)d_in[17];
    const float* freqs = (const float*)d_in[18];
    float* out = (float*)d_out;

    float *ph, *pq, *pk, *pv, *patt, *pff;
    cudaGetSymbolAddress((void**)&ph,   g_h);
    cudaGetSymbolAddress((void**)&pq,   g_q);
    cudaGetSymbolAddress((void**)&pk,   g_k);
    cudaGetSymbolAddress((void**)&pv,   g_v);
    cudaGetSymbolAddress((void**)&patt, g_att);
    cudaGetSymbolAddress((void**)&pff,  g_ff);

    const dim3 gD(D_ / 128, M_ / 128);     // (6, 64)
    const dim3 gF(FF_ / 128, M_ / 128);    // (24, 64)

    // LN1
    ln_kernel<<<M_, 256>>>(x, ln1w, ln1b, ph);
    // QKV projections (tf32 tensor cores)
    gemm_tf32<1><<<gD, 256>>>(ph, wq, bq, nullptr, pq, M_, D_, D_);
    gemm_tf32<0><<<gD, 256>>>(ph, wk, bk, nullptr, pk, M_, D_, D_);
    gemm_tf32<0><<<gD, 256>>>(ph, wv, bv, nullptr, pv, M_, D_, D_);
    // RoPE on q and k
    const int npairs = M_ * (D_ / 2);
    rope_kernel<<<(npairs + 255) / 256, 256>>>(pq, freqs, npairs);
    rope_kernel<<<(npairs + 255) / 256, 256>>>(pk, freqs, npairs);
    // attention
    attn_kernel<<<dim3(N_ / 64, B_ * H_), 256>>>(pq, pk, pv, pmask, patt);
    // O projection + residual (x) -> d_out
    gemm_tf32<3><<<gD, 256>>>(patt, wo, bo, x, out, M_, D_, D_);
    // LN2 (reuse g_h)
    ln_kernel<<<M_, 256>>>(out, ln2w, ln2b, ph);
    // FFN1 with exact GELU
    gemm_tf32<2><<<gF, 256>>>(ph, w1, b1, nullptr, pff, M_, FF_, D_);
    // FFN2 + residual (d_out) -> d_out
    gemm_tf32<3><<<gD, 256>>>(pff, w2, b2, out, out, M_, D_, FF_);
}

// round 4
// speedup vs baseline: 1.7325x; 1.7325x over previous
#include <cuda_runtime.h>
#include <math.h>

#define D_  768
#define H_  12
#define HD_ 64
#define FF_ 3072
#define B_  8
#define N_  1024
#define M_  (B_*N_)          // 8192 rows
#define SCALING_ 0.125f      // HD^-0.5
#define EPS_ 1e-5f

// ---------------- scratch (static device globals; no allocation) -------------
__device__ float g_h  [M_*D_];   // LN1 out, reused as LN2 out
__device__ float g_q  [M_*D_];
__device__ float g_k  [M_*D_];
__device__ float g_v  [M_*D_];
__device__ float g_att[M_*D_];
__device__ float g_ff [M_*FF_];

// ---------------- LayerNorm: one block per row -------------------------------
__global__ __launch_bounds__(256)
void ln_kernel(const float* __restrict__ x, const float* __restrict__ w,
               const float* __restrict__ b, float* __restrict__ out) {
    const int row = blockIdx.x;
    const int tid = threadIdx.x;
    const float* xr = x + (size_t)row * D_;
    float v[3];
    float s = 0.f;
    #pragma unroll
    for (int i = 0; i < 3; i++) { v[i] = xr[tid + i*256]; s += v[i]; }

    __shared__ float red[8];
    __shared__ float bc[2];
    #pragma unroll
    for (int o = 16; o; o >>= 1) s += __shfl_xor_sync(0xffffffffu, s, o);
    if ((tid & 31) == 0) red[tid >> 5] = s;
    __syncthreads();
    if (tid == 0) {
        float t = 0.f;
        #pragma unroll
        for (int i = 0; i < 8; i++) t += red[i];
        bc[0] = t * (1.0f / D_);
    }
    __syncthreads();
    const float mu = bc[0];

    float s2 = 0.f;
    #pragma unroll
    for (int i = 0; i < 3; i++) { float d = v[i] - mu; s2 += d * d; }
    #pragma unroll
    for (int o = 16; o; o >>= 1) s2 += __shfl_xor_sync(0xffffffffu, s2, o);
    if ((tid & 31) == 0) red[tid >> 5] = s2;
    __syncthreads();
    if (tid == 0) {
        float t = 0.f;
        #pragma unroll
        for (int i = 0; i < 8; i++) t += red[i];
        bc[1] = rsqrtf(t * (1.0f / D_) + EPS_);
    }
    __syncthreads();
    const float rstd = bc[1];

    float* orow = out + (size_t)row * D_;
    #pragma unroll
    for (int i = 0; i < 3; i++) {
        int c = tid + i*256;
        orow[c] = (v[i] - mu) * rstd * w[c] + b[c];
    }
}

// ---------------- tf32 helpers -----------------------------------------------
__device__ __forceinline__ unsigned f2tf32(float f) {
    unsigned r;
    asm("cvt.rna.tf32.f32 %0, %1;" : "=r"(r) : "f"(f));
    return r;
}

__device__ __forceinline__ void mma_tf32(float& c0, float& c1, float& c2, float& c3,
                                         unsigned a0, unsigned a1, unsigned a2, unsigned a3,
                                         unsigned b0, unsigned b1) {
    asm volatile(
        "mma.sync.aligned.m16n8k8.row.col.f32.tf32.tf32.f32 "
        "{%0,%1,%2,%3}, {%4,%5,%6,%7}, {%8,%9}, {%0,%1,%2,%3};"
        : "+f"(c0), "+f"(c1), "+f"(c2), "+f"(c3)
        : "r"(a0), "r"(a1), "r"(a2), "r"(a3), "r"(b0), "r"(b1));
}

// ---------------- tf32 NT GEMM: C[M,N] = A[M,K] @ W[N,K]^T + bias ------------
// 128x128 CTA tile, 8 warps (2x4), warp tile 64x32, k-step 16, double buffered.
// Smem layout per row (16 words): logical quad lq (0..3) holds k = {lq, lq+4, lq+8, lq+12},
// physical quad = lq ^ ((row>>1)&3)  (XOR swizzle at float4 granularity).
//  - producer stores element i (k = sub*4+i) to quad (i ^ ((row>>1)&3)), word sub:
//    within a warp (row&1,(row>>1)&3) hits all 8 combos -> 32 distinct banks, conflict-free.
//  - consumer does ONE LDS.128 per fragment group at quad (qk ^ ((row>>1)&3)):
//    per 8-lane phase the swizzle is constant, quads permute -> conflict-free.
// EP: 0 = plain, 1 = *SCALING, 2 = exact GELU, 3 = + res[r,c]
template<int EP>
__global__ __launch_bounds__(256, 2)
void gemm_tf32(const float* __restrict__ A, const float* __restrict__ W,
               const float* __restrict__ bias, const float* __restrict__ res,
               float* __restrict__ C, int M, int N, int K) {
    __shared__ unsigned As[2][128][16];
    __shared__ unsigned Ws[2][128][16];

    const int tid  = threadIdx.x;
    const int lane = tid & 31;
    const int warp = tid >> 5;
    const int wm = (warp >> 2) * 64;   // 0 or 64
    const int wn = (warp & 3) * 32;    // 0,32,64,96
    const int grp = lane >> 2;         // 0..7
    const int qk  = lane & 3;          // 0..3

    const int m0 = blockIdx.y << 7, n0 = blockIdx.x << 7;

    // producer mapping: rows ldr and ldr+64, k-quad sub
    const int ldr = tid >> 2;
    const int sub = tid & 3;
    const float* Ap0 = A + (size_t)(m0 + ldr) * K + (sub << 2);
    const float* Ap1 = A + (size_t)(m0 + ldr + 64) * K + (sub << 2);
    const float* Wp0 = W + (size_t)(n0 + ldr) * K + (sub << 2);
    const float* Wp1 = W + (size_t)(n0 + ldr + 64) * K + (sub << 2);
    const int sw0 = ((ldr >> 1) & 3);        // swizzle for row ldr
    const int sw1 = (((ldr + 64) >> 1) & 3); // swizzle for row ldr+64

    float acc[4][4][4];   // [mi][ni][frag]
    #pragma unroll
    for (int i = 0; i < 4; i++)
        #pragma unroll
        for (int j = 0; j < 4; j++)
            #pragma unroll
            for (int f = 0; f < 4; f++) acc[i][j][f] = 0.f;

    const int ntiles = K >> 4;

    #define STORE_TILE(buf, a0v, a1v, w0v, w1v)                                              \
        do {                                                                                  \
            As[buf][ldr   ][((0^sw0)<<2)+sub]=f2tf32(a0v.x); As[buf][ldr   ][((1^sw0)<<2)+sub]=f2tf32(a0v.y); \
            As[buf][ldr   ][((2^sw0)<<2)+sub]=f2tf32(a0v.z); As[buf][ldr   ][((3^sw0)<<2)+sub]=f2tf32(a0v.w); \
            As[buf][ldr+64][((0^sw1)<<2)+sub]=f2tf32(a1v.x); As[buf][ldr+64][((1^sw1)<<2)+sub]=f2tf32(a1v.y); \
            As[buf][ldr+64][((2^sw1)<<2)+sub]=f2tf32(a1v.z); As[buf][ldr+64][((3^sw1)<<2)+sub]=f2tf32(a1v.w); \
            Ws[buf][ldr   ][((0^sw0)<<2)+sub]=f2tf32(w0v.x); Ws[buf][ldr   ][((1^sw0)<<2)+sub]=f2tf32(w0v.y); \
            Ws[buf][ldr   ][((2^sw0)<<2)+sub]=f2tf32(w0v.z); Ws[buf][ldr   ][((3^sw0)<<2)+sub]=f2tf32(w0v.w); \
            Ws[buf][ldr+64][((0^sw1)<<2)+sub]=f2tf32(w1v.x); Ws[buf][ldr+64][((1^sw1)<<2)+sub]=f2tf32(w1v.y); \
            Ws[buf][ldr+64][((2^sw1)<<2)+sub]=f2tf32(w1v.z); Ws[buf][ldr+64][((3^sw1)<<2)+sub]=f2tf32(w1v.w); \
        } while (0)

    // prologue
    {
        float4 a0 = *(const float4*)(Ap0);
        float4 a1 = *(const float4*)(Ap1);
        float4 w0 = *(const float4*)(Wp0);
        float4 w1 = *(const float4*)(Wp1);
        STORE_TILE(0, a0, a1, w0, w1);
    }
    __syncthreads();

    for (int it = 0; it < ntiles; it++) {
        const int cur = it & 1, nxt = cur ^ 1;
        float4 a0, a1, w0, w1;
        const bool have_next = (it + 1) < ntiles;
        if (have_next) {
            const int ko = (it + 1) << 4;
            a0 = *(const float4*)(Ap0 + ko);
            a1 = *(const float4*)(Ap1 + ko);
            w0 = *(const float4*)(Wp0 + ko);
            w1 = *(const float4*)(Wp1 + ko);
        }

        // B fragments: 4 LDS.128, stay resident
        uint4 Bv[4];
        #pragma unroll
        for (int ni = 0; ni < 4; ni++) {
            const int rn = wn + (ni << 3) + grp;
            Bv[ni] = *(const uint4*)&Ws[cur][rn][((qk ^ ((rn >> 1) & 3)) << 2)];
        }
        // A fragments per mi (2 LDS.128), then 8 MMAs
        #pragma unroll
        for (int mi = 0; mi < 4; mi++) {
            const int rl = wm + (mi << 4) + grp;
            const int rh = rl + 8;
            const uint4 Alo = *(const uint4*)&As[cur][rl][((qk ^ ((rl >> 1) & 3)) << 2)];
            const uint4 Ahi = *(const uint4*)&As[cur][rh][((qk ^ ((rh >> 1) & 3)) << 2)];
            #pragma unroll
            for (int ni = 0; ni < 4; ni++) {
                mma_tf32(acc[mi][ni][0], acc[mi][ni][1], acc[mi][ni][2], acc[mi][ni][3],
                         Alo.x, Ahi.x, Alo.y, Ahi.y, Bv[ni].x, Bv[ni].y);
                mma_tf32(acc[mi][ni][0], acc[mi][ni][1], acc[mi][ni][2], acc[mi][ni][3],
                         Alo.z, Ahi.z, Alo.w, Ahi.w, Bv[ni].z, Bv[ni].w);
            }
        }

        if (have_next) {
            STORE_TILE(nxt, a0, a1, w0, w1);
        }
        __syncthreads();
    }
    #undef STORE_TILE

    // epilogue
    #pragma unroll
    for (int mi = 0; mi < 4; mi++) {
        #pragma unroll
        for (int ni = 0; ni < 4; ni++) {
            #pragma unroll
            for (int f = 0; f < 4; f++) {
                const int r = m0 + wm + (mi << 4) + grp + ((f >> 1) << 3);
                const int c = n0 + wn + (ni << 3) + (qk << 1) + (f & 1);
                float val = acc[mi][ni][f] + bias[c];
                if (EP == 1) val *= SCALING_;
                if (EP == 2) val = 0.5f * val * (1.0f + erff(val * 0.70710678118654752f));
                if (EP == 3) val += res[(size_t)r * N + c];
                C[(size_t)r * N + c] = val;
            }
        }
    }
}

// ---------------- RoPE (interleaved pairs), in-place -------------------------
__global__ void rope_kernel(float* __restrict__ t, const float* __restrict__ freqs, int npairs) {
    int idx = blockIdx.x * blockDim.x + threadIdx.x;
    if (idx >= npairs) return;
    const int row = idx / (D_ / 2);
    const int p   = idx - row * (D_ / 2);
    const int i   = p & 31;
    const int n   = row & (N_ - 1);
    const float ang = (float)n * freqs[i];
    const float c = cosf(ang), s = sinf(ang);
    float* base = t + (size_t)row * D_ + p * 2;
    const float x0 = base[0], x1 = base[1];
    base[0] = x0 * c - x1 * s;
    base[1] = x1 * c + x0 * s;
}

// ---------------- flash attention, fp32, BQ=64 BK=32 -------------------------
__device__ __forceinline__ float rmax16(float v) {
    #pragma unroll
    for (int o = 8; o; o >>= 1) v = fmaxf(v, __shfl_xor_sync(0xffffffffu, v, o, 16));
    return v;
}
__device__ __forceinline__ float rsum16(float v) {
    #pragma unroll
    for (int o = 8; o; o >>= 1) v += __shfl_xor_sync(0xffffffffu, v, o, 16);
    return v;
}

__global__ __launch_bounds__(256)
void attn_kernel(const float* __restrict__ q, const float* __restrict__ k,
                 const float* __restrict__ v, const unsigned char* __restrict__ pm,
                 float* __restrict__ out) {
    __shared__ float Qs[64][65];
    __shared__ float Ks[64][33];
    __shared__ float Vs[32][68];
    __shared__ float Ps[64][33];
    __shared__ unsigned char Ms[32];

    const int tid = threadIdx.x;
    const int tx = tid & 15, ty = tid >> 4;
    const int qt = blockIdx.x, bh = blockIdx.y;
    const int b = bh / H_, h = bh - b * H_;
    const int row0 = b * N_ + qt * 64;
    const int colh = h * HD_;

    for (int idx = tid; idx < 64 * 64; idx += 256) {
        const int r = idx >> 6, d = idx & 63;
        Qs[d][r] = q[(size_t)(row0 + r) * D_ + colh + d];
    }

    float o[4][4];
    #pragma unroll
    for (int i = 0; i < 4; i++)
        #pragma unroll
        for (int j = 0; j < 4; j++) o[i][j] = 0.f;
    float mreg[4], lreg[4];
    #pragma unroll
    for (int i = 0; i < 4; i++) { mreg[i] = -3.0e38f; lreg[i] = 0.f; }

    const int r0  = ty << 2;
    const int c0s = tx << 1;
    const int c0o = tx << 2;

    for (int kt = 0; kt < N_; kt += 32) {
        for (int idx = tid; idx < 32 * 64; idx += 256) {
            const int c = idx >> 6, d = idx & 63;
            const size_t g = (size_t)(b * N_ + kt + c) * D_ + colh + d;
            Ks[d][c] = k[g];
            Vs[c][d] = v[g];
        }
        if (tid < 32) Ms[tid] = pm[b * N_ + kt + tid];
        __syncthreads();

        float s[4][2];
        s[0][0]=s[0][1]=s[1][0]=s[1][1]=s[2][0]=s[2][1]=s[3][0]=s[3][1]=0.f;
        #pragma unroll 4
        for (int d = 0; d < 64; d++) {
            const float a0 = Qs[d][r0], a1 = Qs[d][r0+1], a2 = Qs[d][r0+2], a3 = Qs[d][r0+3];
            const float b0 = Ks[d][c0s], b1 = Ks[d][c0s+1];
            s[0][0] = fmaf(a0, b0, s[0][0]); s[0][1] = fmaf(a0, b1, s[0][1]);
            s[1][0] = fmaf(a1, b0, s[1][0]); s[1][1] = fmaf(a1, b1, s[1][1]);
            s[2][0] = fmaf(a2, b0, s[2][0]); s[2][1] = fmaf(a2, b1, s[2][1]);
            s[3][0] = fmaf(a3, b0, s[3][0]); s[3][1] = fmaf(a3, b1, s[3][1]);
        }
        const bool msk0 = Ms[c0s] != 0, msk1 = Ms[c0s+1] != 0;
        #pragma unroll
        for (int i = 0; i < 4; i++) {
            s[i][0] = msk0 ? -3.0e38f : s[i][0] * 0.125f;
            s[i][1] = msk1 ? -3.0e38f : s[i][1] * 0.125f;
        }

        #pragma unroll
        for (int i = 0; i < 4; i++) {
            float mt = rmax16(fmaxf(s[i][0], s[i][1]));
            const float mnew = fmaxf(mreg[i], mt);
            const float alpha = __expf(mreg[i] - mnew);
            const float p0 = __expf(s[i][0] - mnew);
            const float p1 = __expf(s[i][1] - mnew);
            const float rs = rsum16(p0 + p1);
            lreg[i] = lreg[i] * alpha + rs;
            mreg[i] = mnew;
            #pragma unroll
            for (int j = 0; j < 4; j++) o[i][j] *= alpha;
            Ps[r0 + i][c0s]     = p0;
            Ps[r0 + i][c0s + 1] = p1;
        }
        __syncthreads();

        #pragma unroll 4
        for (int kk = 0; kk < 32; kk++) {
            const float4 vv = *(const float4*)&Vs[kk][c0o];
            const float p0 = Ps[r0][kk],   p1 = Ps[r0+1][kk];
            const float p2 = Ps[r0+2][kk], p3 = Ps[r0+3][kk];
            o[0][0] = fmaf(p0, vv.x, o[0][0]); o[0][1] = fmaf(p0, vv.y, o[0][1]);
            o[0][2] = fmaf(p0, vv.z, o[0][2]); o[0][3] = fmaf(p0, vv.w, o[0][3]);
            o[1][0] = fmaf(p1, vv.x, o[1][0]); o[1][1] = fmaf(p1, vv.y, o[1][1]);
            o[1][2] = fmaf(p1, vv.z, o[1][2]); o[1][3] = fmaf(p1, vv.w, o[1][3]);
            o[2][0] = fmaf(p2, vv.x, o[2][0]); o[2][1] = fmaf(p2, vv.y, o[2][1]);
            o[2][2] = fmaf(p2, vv.z, o[2][2]); o[2][3] = fmaf(p2, vv.w, o[2][3]);
            o[3][0] = fmaf(p3, vv.x, o[3][0]); o[3][1] = fmaf(p3, vv.y, o[3][1]);
            o[3][2] = fmaf(p3, vv.z, o[3][2]); o[3][3] = fmaf(p3, vv.w, o[3][3]);
        }
        __syncthreads();
    }

    #pragma unroll
    for (int i = 0; i < 4; i++) {
        const float inv = 1.0f / lreg[i];
        float4 r4;
        r4.x = o[i][0] * inv; r4.y = o[i][1] * inv;
        r4.z = o[i][2] * inv; r4.w = o[i][3] * inv;
        *(float4*)&out[(size_t)(row0 + r0 + i) * D_ + colh + c0o] = r4;
    }
}

// ---------------- launch ------------------------------------------------------
extern "C" void kernel_launch(void* const* d_in, const int* in_sizes, int n_in,
                              void* d_out, int out_size) {
    const float* x     = (const float*)d_in[0];
    const unsigned char* pmask = (const unsigned char*)d_in[1];
    const float* wq = (const float*)d_in[2];
    const float* bq = (const float*)d_in[3];
    const float* wk = (const float*)d_in[4];
    const float* bk = (const float*)d_in[5];
    const float* wv = (const float*)d_in[6];
    const float* bv = (const float*)d_in[7];
    const float* wo = (const float*)d_in[8];
    const float* bo = (const float*)d_in[9];
    const float* w1 = (const float*)d_in[10];
    const float* b1 = (const float*)d_in[11];
    const float* w2 = (const float*)d_in[12];
    const float* b2 = (const float*)d_in[13];
    const float* ln1w = (const float*)d_in[14];
    const float* ln1b = (const float*)d_in[15];
    const float* ln2w = (const float*)d_in[16];
    const float* ln2b = (const float*)d_in[17];
    const float* freqs = (const float*)d_in[18];
    float* out = (float*)d_out;

    float *ph, *pq, *pk, *pv, *patt, *pff;
    cudaGetSymbolAddress((void**)&ph,   g_h);
    cudaGetSymbolAddress((void**)&pq,   g_q);
    cudaGetSymbolAddress((void**)&pk,   g_k);
    cudaGetSymbolAddress((void**)&pv,   g_v);
    cudaGetSymbolAddress((void**)&patt, g_att);
    cudaGetSymbolAddress((void**)&pff,  g_ff);

    const dim3 gD(D_ / 128, M_ / 128);     // (6, 64)
    const dim3 gF(FF_ / 128, M_ / 128);    // (24, 64)

    // LN1
    ln_kernel<<<M_, 256>>>(x, ln1w, ln1b, ph);
    // QKV projections (tf32 tensor cores)
    gemm_tf32<1><<<gD, 256>>>(ph, wq, bq, nullptr, pq, M_, D_, D_);
    gemm_tf32<0><<<gD, 256>>>(ph, wk, bk, nullptr, pk, M_, D_, D_);
    gemm_tf32<0><<<gD, 256>>>(ph, wv, bv, nullptr, pv, M_, D_, D_);
    // RoPE on q and k
    const int npairs = M_ * (D_ / 2);
    rope_kernel<<<(npairs + 255) / 256, 256>>>(pq, freqs, npairs);
    rope_kernel<<<(npairs + 255) / 256, 256>>>(pk, freqs, npairs);
    // attention
    attn_kernel<<<dim3(N_ / 64, B_ * H_), 256>>>(pq, pk, pv, pmask, patt);
    // O projection + residual (x) -> d_out
    gemm_tf32<3><<<gD, 256>>>(patt, wo, bo, x, out, M_, D_, D_);
    // LN2 (reuse g_h)
    ln_kernel<<<M_, 256>>>(out, ln2w, ln2b, ph);
    // FFN1 with exact GELU
    gemm_tf32<2><<<gF, 256>>>(ph, w1, b1, nullptr, pff, M_, FF_, D_);
    // FFN2 + residual (d_out) -> d_out
    gemm_tf32<3><<<gD, 256>>>(pff, w2, b2, out, out, M_, D_, FF_);
}

// round 6
// speedup vs baseline: 2.0756x; 1.1981x over previous
#include <cuda_runtime.h>
#include <math.h>
#include <stdint.h>

#define D_  768
#define H_  12
#define HD_ 64
#define FF_ 3072
#define B_  8
#define N_  1024
#define M_  (B_*N_)          // 8192 rows
#define SCALING_ 0.125f      // HD^-0.5
#define EPS_ 1e-5f

// tcgen05 availability: only on arch-specific / family-specific compilation passes.
#if defined(__CUDA_ARCH_FEAT_SM103_ALL) || defined(__CUDA_ARCH_FEAT_SM100_ALL) || \
    defined(__CUDA_ARCH_SPECIFIC__) || defined(__CUDA_ARCH_FAMILY_SPECIFIC__)
#define TC_OK 1
#else
#define TC_OK 0
#endif

// ---------------- scratch (static device globals; no allocation) -------------
__device__ float g_h  [M_*D_];
__device__ float g_q  [M_*D_];
__device__ float g_k  [M_*D_];
__device__ float g_v  [M_*D_];
__device__ float g_att[M_*D_];
__device__ float g_ff [M_*FF_];

// ---------------- common helpers ---------------------------------------------
__device__ __forceinline__ unsigned f2tf32(float f) {
    unsigned r;
    asm("cvt.rna.tf32.f32 %0, %1;" : "=r"(r) : "f"(f));
    return r;
}

#if TC_OK
__device__ __forceinline__ uint32_t smem_u32(const void* p) {
    uint32_t a;
    asm("{ .reg .u64 t; cvta.to.shared.u64 t, %1; cvt.u32.u64 %0, t; }" : "=r"(a) : "l"(p));
    return a;
}
__device__ __forceinline__ uint32_t elect_one() {
    uint32_t p;
    asm volatile("{ .reg .pred p; elect.sync _|p, 0xFFFFFFFF; selp.b32 %0, 1, 0, p; }" : "=r"(p));
    return p;
}
#define TC_ALLOC(smem_addr, n) \
    asm volatile("tcgen05.alloc.cta_group::1.sync.aligned.shared::cta.b32 [%0], %1;" \
                 :: "r"(smem_addr), "r"((uint32_t)(n)) : "memory")
#define TC_RELINQ() \
    asm volatile("tcgen05.relinquish_alloc_permit.cta_group::1.sync.aligned;")
#define TC_DEALLOC(tmem, n) \
    asm volatile("tcgen05.dealloc.cta_group::1.sync.aligned.b32 %0, %1;" :: "r"(tmem), "r"((uint32_t)(n)))
#define TC_COMMIT(mbar) \
    asm volatile("tcgen05.commit.cta_group::1.mbarrier::arrive::one.shared::cluster.b64 [%0];" \
                 :: "r"(mbar) : "memory")
#define TC_FENCE_AFTER()  asm volatile("tcgen05.fence::after_thread_sync;" ::: "memory")
#define FENCE_ASYNC_SH()  asm volatile("fence.proxy.async.shared::cta;" ::: "memory")
#define MBAR_INIT(mbar, cnt) \
    asm volatile("mbarrier.init.shared.b64 [%0], %1;" :: "r"(mbar), "r"((uint32_t)(cnt)) : "memory")
#define MBAR_WAIT(mbar, ph) do {                                                  \
    asm volatile("{\n\t.reg .pred P1;\n\t"                                        \
        "WL_%=:\n\t"                                                              \
        "mbarrier.try_wait.parity.acquire.cta.shared::cta.b64 P1, [%0], %1, 0x989680;\n\t" \
        "@P1 bra.uni WD_%=;\n\t"                                                  \
        "bra.uni WL_%=;\n\t"                                                      \
        "WD_%=:\n\t}"                                                             \
        :: "r"(mbar), "r"((uint32_t)(ph)) : "memory");                            \
} while (0)
#define TC_LD_X32(r, tmem) \
    asm volatile( \
        "tcgen05.ld.sync.aligned.32x32b.x32.b32 " \
        "{%0, %1, %2, %3, %4, %5, %6, %7, " \
        " %8, %9, %10, %11, %12, %13, %14, %15, " \
        " %16, %17, %18, %19, %20, %21, %22, %23, " \
        " %24, %25, %26, %27, %28, %29, %30, %31}, [%32];" \
        : "=r"((r)[0]),  "=r"((r)[1]),  "=r"((r)[2]),  "=r"((r)[3]), \
          "=r"((r)[4]),  "=r"((r)[5]),  "=r"((r)[6]),  "=r"((r)[7]), \
          "=r"((r)[8]),  "=r"((r)[9]),  "=r"((r)[10]), "=r"((r)[11]), \
          "=r"((r)[12]), "=r"((r)[13]), "=r"((r)[14]), "=r"((r)[15]), \
          "=r"((r)[16]), "=r"((r)[17]), "=r"((r)[18]), "=r"((r)[19]), \
          "=r"((r)[20]), "=r"((r)[21]), "=r"((r)[22]), "=r"((r)[23]), \
          "=r"((r)[24]), "=r"((r)[25]), "=r"((r)[26]), "=r"((r)[27]), \
          "=r"((r)[28]), "=r"((r)[29]), "=r"((r)[30]), "=r"((r)[31]) \
        : "r"(tmem))
#define TC_WAIT_LD() asm volatile("tcgen05.wait::ld.sync.aligned;" ::: "memory")

__device__ __forceinline__ void tc_mma_tf32_ss(uint32_t d, uint64_t ad, uint64_t bd,
                                               uint32_t idesc, bool acc) {
    uint32_t e = acc ? 1u : 0u;
    asm volatile(
        "{\n\t.reg .pred p;\n\tsetp.ne.u32 p, %4, 0;\n\t"
        "tcgen05.mma.cta_group::1.kind::tf32 [%0], %1, %2, %3, {%5,%5,%5,%5}, p;\n\t}"
        :: "r"(d), "l"(ad), "l"(bd), "r"(idesc), "r"(e), "r"(0u) : "memory");
}
// SW128 K-major smem descriptor: layout=2, version=1, SBO=64, LBO=1
__device__ __forceinline__ uint64_t mk_desc(uint32_t addr) {
    const uint64_t base = (uint64_t(2) << 61) | (uint64_t(1) << 46)
                        | (uint64_t(64) << 32) | (uint64_t(1) << 16);
    return base | ((uint64_t)(addr >> 4) & 0x3FFF);
}
#define SWZ128(b) ((b) ^ (((b) >> 3) & 0x70))
// idesc: cfmt=F32(1)<<4, a=TF32(2)<<7, b=TF32(2)<<10, N=128 ->16<<17, M=128 ->8<<24
#define TC_IDESC ((1u<<4)|(2u<<7)|(2u<<10)|(16u<<17)|(8u<<24))
#endif  // TC_OK

__device__ __forceinline__ void mma_tf32(float& c0, float& c1, float& c2, float& c3,
                                         unsigned a0, unsigned a1, unsigned a2, unsigned a3,
                                         unsigned b0, unsigned b1) {
    asm volatile(
        "mma.sync.aligned.m16n8k8.row.col.f32.tf32.tf32.f32 "
        "{%0,%1,%2,%3}, {%4,%5,%6,%7}, {%8,%9}, {%0,%1,%2,%3};"
        : "+f"(c0), "+f"(c1), "+f"(c2), "+f"(c3)
        : "r"(a0), "r"(a1), "r"(a2), "r"(a3), "r"(b0), "r"(b1));
}

// ---------------- LayerNorm: one block per row -------------------------------
__global__ __launch_bounds__(256)
void ln_kernel(const float* __restrict__ x, const float* __restrict__ w,
               const float* __restrict__ b, float* __restrict__ out) {
    const int row = blockIdx.x;
    const int tid = threadIdx.x;
    const float* xr = x + (size_t)row * D_;
    float v[3];
    float s = 0.f;
    #pragma unroll
    for (int i = 0; i < 3; i++) { v[i] = xr[tid + i*256]; s += v[i]; }

    __shared__ float red[8];
    __shared__ float bc[2];
    #pragma unroll
    for (int o = 16; o; o >>= 1) s += __shfl_xor_sync(0xffffffffu, s, o);
    if ((tid & 31) == 0) red[tid >> 5] = s;
    __syncthreads();
    if (tid == 0) {
        float t = 0.f;
        #pragma unroll
        for (int i = 0; i < 8; i++) t += red[i];
        bc[0] = t * (1.0f / D_);
    }
    __syncthreads();
    const float mu = bc[0];

    float s2 = 0.f;
    #pragma unroll
    for (int i = 0; i < 3; i++) { float d = v[i] - mu; s2 += d * d; }
    #pragma unroll
    for (int o = 16; o; o >>= 1) s2 += __shfl_xor_sync(0xffffffffu, s2, o);
    if ((tid & 31) == 0) red[tid >> 5] = s2;
    __syncthreads();
    if (tid == 0) {
        float t = 0.f;
        #pragma unroll
        for (int i = 0; i < 8; i++) t += red[i];
        bc[1] = rsqrtf(t * (1.0f / D_) + EPS_);
    }
    __syncthreads();
    const float rstd = bc[1];

    float* orow = out + (size_t)row * D_;
    #pragma unroll
    for (int i = 0; i < 3; i++) {
        int c = tid + i*256;
        orow[c] = (v[i] - mu) * rstd * w[c] + b[c];
    }
}

// ---------------- unified tf32 NT GEMM ---------------------------------------
// C[M,N] = A[M,K] @ W[N,K]^T + bias. 128x128 tile/CTA.
// TC_OK:  tcgen05 SS MMA, K staged in 32-float (128B) SW128 slices, double
//         buffered, accumulator in TMEM, LDTM epilogue.
// else :  R4 mma.sync path (XOR-swizzled smem, LDS.128 fragments).
// EP: 0 = plain, 1 = *SCALING, 2 = exact GELU, 3 = + res[r,c]
#define STAGE_BYTES 16384
#define GEMM_DYN_SMEM (4*STAGE_BYTES + 1024)

template<int EP>
__global__ __launch_bounds__(256, 2)
void gemm_u(const float* __restrict__ A, const float* __restrict__ W,
            const float* __restrict__ bias, const float* __restrict__ res,
            float* __restrict__ C, int M, int N, int K) {
#if TC_OK
    extern __shared__ char dsm[];
    __shared__ uint32_t tmem_ptr_s[1];
    __shared__ __align__(8) uint64_t mbar_s[2];

    const int tid  = threadIdx.x;
    const int warp = tid >> 5;
    const int lane = tid & 31;
    const int m0 = blockIdx.y << 7, n0 = blockIdx.x << 7;

    // 1KB-align dynamic smem base (SW128 descriptor requirement)
    uint32_t rawb = smem_u32(dsm);
    uint32_t ab   = (rawb + 1023u) & ~1023u;
    char* sbase = dsm + (ab - rawb);
    char* sA[2] = { sbase,                 sbase + STAGE_BYTES };
    char* sB[2] = { sbase + 2*STAGE_BYTES, sbase + 3*STAGE_BYTES };
    const uint32_t aAddr[2] = { ab, ab + STAGE_BYTES };
    const uint32_t bAddr[2] = { ab + 2*STAGE_BYTES, ab + 3*STAGE_BYTES };
    const uint32_t mbar0 = smem_u32(&mbar_s[0]);
    const uint32_t mbar1 = smem_u32(&mbar_s[1]);

    if (warp == 0) {
        TC_ALLOC(smem_u32(tmem_ptr_s), 128);
        TC_RELINQ();
    }
    if (tid == 0) { MBAR_INIT(mbar0, 1); MBAR_INIT(mbar1, 1); }
    __syncthreads();
    uint32_t tmem;
    asm volatile("ld.shared.b32 %0, [%1];" : "=r"(tmem) : "r"(smem_u32(tmem_ptr_s)));

    const int prow = tid >> 3;   // 0..31 (+32p)
    const int psub = tid & 7;    // 16B chunk in 128B row

    const int nst = K >> 5;      // 32 floats per stage
    for (int s = 0; s < nst; s++) {
        const int b = s & 1;
        if (s >= 2) MBAR_WAIT(b ? mbar1 : mbar0, ((s - 2) >> 1) & 1);
        const int k0 = s << 5;
        #pragma unroll
        for (int p = 0; p < 4; p++) {
            const int r = prow + (p << 5);
            const float4 av = *(const float4*)(A + (size_t)(m0 + r) * K + k0 + (psub << 2));
            const float4 wv = *(const float4*)(W + (size_t)(n0 + r) * K + k0 + (psub << 2));
            const uint32_t off = SWZ128((r << 7) | (psub << 4));
            uint4 at, wt;
            at.x = f2tf32(av.x); at.y = f2tf32(av.y); at.z = f2tf32(av.z); at.w = f2tf32(av.w);
            wt.x = f2tf32(wv.x); wt.y = f2tf32(wv.y); wt.z = f2tf32(wv.z); wt.w = f2tf32(wv.w);
            *(uint4*)(sA[b] + off) = at;
            *(uint4*)(sB[b] + off) = wt;
        }
        FENCE_ASYNC_SH();
        __syncthreads();
        if (warp == 0 && elect_one()) {
            const uint64_t ad = mk_desc(aAddr[b]);
            const uint64_t bd = mk_desc(bAddr[b]);
            #pragma unroll
            for (int k = 0; k < 4; k++)
                tc_mma_tf32_ss(tmem, ad + k*2, bd + k*2, TC_IDESC, (s > 0) || (k > 0));
            TC_COMMIT(b ? mbar1 : mbar0);
        }
        __syncthreads();
    }

    const int ls = nst - 1;
    MBAR_WAIT((ls & 1) ? mbar1 : mbar0, (ls >> 1) & 1);
    TC_FENCE_AFTER();

    // epilogue: warp w -> rows (w&3)*32 + lane, cols (w>>2)*64 .. +63
    uint32_t dr[64];
    const int cb = (warp >> 2) << 6;
    TC_LD_X32(dr,      tmem + cb);
    TC_LD_X32(dr + 32, tmem + cb + 32);
    TC_WAIT_LD();

    const int r  = m0 + ((warp & 3) << 5) + lane;
    const int cg = n0 + cb;
    float* crow = C + (size_t)r * N + cg;
    const float* rrow = (EP == 3) ? (res + (size_t)r * N + cg) : nullptr;
    #pragma unroll
    for (int j4 = 0; j4 < 16; j4++) {
        float4 bv = *(const float4*)(bias + cg + (j4 << 2));
        float4 o;
        o.x = __uint_as_float(dr[j4*4+0]) + bv.x;
        o.y = __uint_as_float(dr[j4*4+1]) + bv.y;
        o.z = __uint_as_float(dr[j4*4+2]) + bv.z;
        o.w = __uint_as_float(dr[j4*4+3]) + bv.w;
        if (EP == 1) { o.x *= SCALING_; o.y *= SCALING_; o.z *= SCALING_; o.w *= SCALING_; }
        if (EP == 2) {
            o.x = 0.5f * o.x * (1.0f + erff(o.x * 0.70710678118654752f));
            o.y = 0.5f * o.y * (1.0f + erff(o.y * 0.70710678118654752f));
            o.z = 0.5f * o.z * (1.0f + erff(o.z * 0.70710678118654752f));
            o.w = 0.5f * o.w * (1.0f + erff(o.w * 0.70710678118654752f));
        }
        if (EP == 3) {
            float4 rv = *(const float4*)(rrow + (j4 << 2));
            o.x += rv.x; o.y += rv.y; o.z += rv.z; o.w += rv.w;
        }
        *(float4*)(crow + (j4 << 2)) = o;
    }

    __syncthreads();
    if (warp == 0) TC_DEALLOC(tmem, 128);

#else  // ---------------- fallback: R4 mma.sync path --------------------------
    extern __shared__ char dsm[];
    typedef unsigned SmemBuf[128][16];
    SmemBuf* As = reinterpret_cast<SmemBuf*>(dsm);                       // [2][128][16]
    SmemBuf* Ws = reinterpret_cast<SmemBuf*>(dsm + 2 * sizeof(SmemBuf)); // [2][128][16]

    const int tid  = threadIdx.x;
    const int lane = tid & 31;
    const int warp = tid >> 5;
    const int wm = (warp >> 2) * 64;
    const int wn = (warp & 3) * 32;
    const int grp = lane >> 2;
    const int qk  = lane & 3;

    const int m0 = blockIdx.y << 7, n0 = blockIdx.x << 7;

    const int ldr = tid >> 2;
    const int sub = tid & 3;
    const float* Ap0 = A + (size_t)(m0 + ldr) * K + (sub << 2);
    const float* Ap1 = A + (size_t)(m0 + ldr + 64) * K + (sub << 2);
    const float* Wp0 = W + (size_t)(n0 + ldr) * K + (sub << 2);
    const float* Wp1 = W + (size_t)(n0 + ldr + 64) * K + (sub << 2);
    const int sw0 = ((ldr >> 1) & 3);
    const int sw1 = (((ldr + 64) >> 1) & 3);

    float acc[4][4][4];
    #pragma unroll
    for (int i = 0; i < 4; i++)
        #pragma unroll
        for (int j = 0; j < 4; j++)
            #pragma unroll
            for (int f = 0; f < 4; f++) acc[i][j][f] = 0.f;

    const int ntiles = K >> 4;

    #define STORE_TILE(buf, a0v, a1v, w0v, w1v)                                              \
        do {                                                                                  \
            As[buf][ldr   ][((0^sw0)<<2)+sub]=f2tf32(a0v.x); As[buf][ldr   ][((1^sw0)<<2)+sub]=f2tf32(a0v.y); \
            As[buf][ldr   ][((2^sw0)<<2)+sub]=f2tf32(a0v.z); As[buf][ldr   ][((3^sw0)<<2)+sub]=f2tf32(a0v.w); \
            As[buf][ldr+64][((0^sw1)<<2)+sub]=f2tf32(a1v.x); As[buf][ldr+64][((1^sw1)<<2)+sub]=f2tf32(a1v.y); \
            As[buf][ldr+64][((2^sw1)<<2)+sub]=f2tf32(a1v.z); As[buf][ldr+64][((3^sw1)<<2)+sub]=f2tf32(a1v.w); \
            Ws[buf][ldr   ][((0^sw0)<<2)+sub]=f2tf32(w0v.x); Ws[buf][ldr   ][((1^sw0)<<2)+sub]=f2tf32(w0v.y); \
            Ws[buf][ldr   ][((2^sw0)<<2)+sub]=f2tf32(w0v.z); Ws[buf][ldr   ][((3^sw0)<<2)+sub]=f2tf32(w0v.w); \
            Ws[buf][ldr+64][((0^sw1)<<2)+sub]=f2tf32(w1v.x); Ws[buf][ldr+64][((1^sw1)<<2)+sub]=f2tf32(w1v.y); \
            Ws[buf][ldr+64][((2^sw1)<<2)+sub]=f2tf32(w1v.z); Ws[buf][ldr+64][((3^sw1)<<2)+sub]=f2tf32(w1v.w); \
        } while (0)

    {
        float4 a0 = *(const float4*)(Ap0);
        float4 a1 = *(const float4*)(Ap1);
        float4 w0 = *(const float4*)(Wp0);
        float4 w1 = *(const float4*)(Wp1);
        STORE_TILE(0, a0, a1, w0, w1);
    }
    __syncthreads();

    for (int it = 0; it < ntiles; it++) {
        const int cur = it & 1, nxt = cur ^ 1;
        float4 a0, a1, w0, w1;
        const bool have_next = (it + 1) < ntiles;
        if (have_next) {
            const int ko = (it + 1) << 4;
            a0 = *(const float4*)(Ap0 + ko);
            a1 = *(const float4*)(Ap1 + ko);
            w0 = *(const float4*)(Wp0 + ko);
            w1 = *(const float4*)(Wp1 + ko);
        }

        uint4 Bv[4];
        #pragma unroll
        for (int ni = 0; ni < 4; ni++) {
            const int rn = wn + (ni << 3) + grp;
            Bv[ni] = *(const uint4*)&Ws[cur][rn][((qk ^ ((rn >> 1) & 3)) << 2)];
        }
        #pragma unroll
        for (int mi = 0; mi < 4; mi++) {
            const int rl = wm + (mi << 4) + grp;
            const int rh = rl + 8;
            const uint4 Alo = *(const uint4*)&As[cur][rl][((qk ^ ((rl >> 1) & 3)) << 2)];
            const uint4 Ahi = *(const uint4*)&As[cur][rh][((qk ^ ((rh >> 1) & 3)) << 2)];
            #pragma unroll
            for (int ni = 0; ni < 4; ni++) {
                mma_tf32(acc[mi][ni][0], acc[mi][ni][1], acc[mi][ni][2], acc[mi][ni][3],
                         Alo.x, Ahi.x, Alo.y, Ahi.y, Bv[ni].x, Bv[ni].y);
                mma_tf32(acc[mi][ni][0], acc[mi][ni][1], acc[mi][ni][2], acc[mi][ni][3],
                         Alo.z, Ahi.z, Alo.w, Ahi.w, Bv[ni].z, Bv[ni].w);
            }
        }

        if (have_next) {
            STORE_TILE(nxt, a0, a1, w0, w1);
        }
        __syncthreads();
    }
    #undef STORE_TILE

    #pragma unroll
    for (int mi = 0; mi < 4; mi++) {
        #pragma unroll
        for (int ni = 0; ni < 4; ni++) {
            #pragma unroll
            for (int f = 0; f < 4; f++) {
                const int r = m0 + wm + (mi << 4) + grp + ((f >> 1) << 3);
                const int c = n0 + wn + (ni << 3) + (qk << 1) + (f & 1);
                float val = acc[mi][ni][f] + bias[c];
                if (EP == 1) val *= SCALING_;
                if (EP == 2) val = 0.5f * val * (1.0f + erff(val * 0.70710678118654752f));
                if (EP == 3) val += res[(size_t)r * N + c];
                C[(size_t)r * N + c] = val;
            }
        }
    }
#endif
}

// ---------------- RoPE (interleaved pairs), in-place -------------------------
__global__ void rope_kernel(float* __restrict__ t, const float* __restrict__ freqs, int npairs) {
    int idx = blockIdx.x * blockDim.x + threadIdx.x;
    if (idx >= npairs) return;
    const int row = idx / (D_ / 2);
    const int p   = idx - row * (D_ / 2);
    const int i   = p & 31;
    const int n   = row & (N_ - 1);
    const float ang = (float)n * freqs[i];
    const float c = cosf(ang), s = sinf(ang);
    float* base = t + (size_t)row * D_ + p * 2;
    const float x0 = base[0], x1 = base[1];
    base[0] = x0 * c - x1 * s;
    base[1] = x1 * c + x0 * s;
}

// ---------------- flash attention, fp32, BQ=64 BK=32 -------------------------
__device__ __forceinline__ float rmax16(float v) {
    #pragma unroll
    for (int o = 8; o; o >>= 1) v = fmaxf(v, __shfl_xor_sync(0xffffffffu, v, o, 16));
    return v;
}
__device__ __forceinline__ float rsum16(float v) {
    #pragma unroll
    for (int o = 8; o; o >>= 1) v += __shfl_xor_sync(0xffffffffu, v, o, 16);
    return v;
}

__global__ __launch_bounds__(256)
void attn_kernel(const float* __restrict__ q, const float* __restrict__ k,
                 const float* __restrict__ v, const unsigned char* __restrict__ pm,
                 float* __restrict__ out) {
    __shared__ float Qs[64][65];
    __shared__ float Ks[64][33];
    __shared__ float Vs[32][68];
    __shared__ float Ps[64][33];
    __shared__ unsigned char Ms[32];

    const int tid = threadIdx.x;
    const int tx = tid & 15, ty = tid >> 4;
    const int qt = blockIdx.x, bh = blockIdx.y;
    const int b = bh / H_, h = bh - b * H_;
    const int row0 = b * N_ + qt * 64;
    const int colh = h * HD_;

    for (int idx = tid; idx < 64 * 64; idx += 256) {
        const int r = idx >> 6, d = idx & 63;
        Qs[d][r] = q[(size_t)(row0 + r) * D_ + colh + d];
    }

    float o[4][4];
    #pragma unroll
    for (int i = 0; i < 4; i++)
        #pragma unroll
        for (int j = 0; j < 4; j++) o[i][j] = 0.f;
    float mreg[4], lreg[4];
    #pragma unroll
    for (int i = 0; i < 4; i++) { mreg[i] = -3.0e38f; lreg[i] = 0.f; }

    const int r0  = ty << 2;
    const int c0s = tx << 1;
    const int c0o = tx << 2;

    for (int kt = 0; kt < N_; kt += 32) {
        for (int idx = tid; idx < 32 * 64; idx += 256) {
            const int c = idx >> 6, d = idx & 63;
            const size_t g = (size_t)(b * N_ + kt + c) * D_ + colh + d;
            Ks[d][c] = k[g];
            Vs[c][d] = v[g];
        }
        if (tid < 32) Ms[tid] = pm[b * N_ + kt + tid];
        __syncthreads();

        float s[4][2];
        s[0][0]=s[0][1]=s[1][0]=s[1][1]=s[2][0]=s[2][1]=s[3][0]=s[3][1]=0.f;
        #pragma unroll 4
        for (int d = 0; d < 64; d++) {
            const float a0 = Qs[d][r0], a1 = Qs[d][r0+1], a2 = Qs[d][r0+2], a3 = Qs[d][r0+3];
            const float b0 = Ks[d][c0s], b1 = Ks[d][c0s+1];
            s[0][0] = fmaf(a0, b0, s[0][0]); s[0][1] = fmaf(a0, b1, s[0][1]);
            s[1][0] = fmaf(a1, b0, s[1][0]); s[1][1] = fmaf(a1, b1, s[1][1]);
            s[2][0] = fmaf(a2, b0, s[2][0]); s[2][1] = fmaf(a2, b1, s[2][1]);
            s[3][0] = fmaf(a3, b0, s[3][0]); s[3][1] = fmaf(a3, b1, s[3][1]);
        }
        const bool msk0 = Ms[c0s] != 0, msk1 = Ms[c0s+1] != 0;
        #pragma unroll
        for (int i = 0; i < 4; i++) {
            s[i][0] = msk0 ? -3.0e38f : s[i][0] * 0.125f;
            s[i][1] = msk1 ? -3.0e38f : s[i][1] * 0.125f;
        }

        #pragma unroll
        for (int i = 0; i < 4; i++) {
            float mt = rmax16(fmaxf(s[i][0], s[i][1]));
            const float mnew = fmaxf(mreg[i], mt);
            const float alpha = __expf(mreg[i] - mnew);
            const float p0 = __expf(s[i][0] - mnew);
            const float p1 = __expf(s[i][1] - mnew);
            const float rs = rsum16(p0 + p1);
            lreg[i] = lreg[i] * alpha + rs;
            mreg[i] = mnew;
            #pragma unroll
            for (int j = 0; j < 4; j++) o[i][j] *= alpha;
            Ps[r0 + i][c0s]     = p0;
            Ps[r0 + i][c0s + 1] = p1;
        }
        __syncthreads();

        #pragma unroll 4
        for (int kk = 0; kk < 32; kk++) {
            const float4 vv = *(const float4*)&Vs[kk][c0o];
            const float p0 = Ps[r0][kk],   p1 = Ps[r0+1][kk];
            const float p2 = Ps[r0+2][kk], p3 = Ps[r0+3][kk];
            o[0][0] = fmaf(p0, vv.x, o[0][0]); o[0][1] = fmaf(p0, vv.y, o[0][1]);
            o[0][2] = fmaf(p0, vv.z, o[0][2]); o[0][3] = fmaf(p0, vv.w, o[0][3]);
            o[1][0] = fmaf(p1, vv.x, o[1][0]); o[1][1] = fmaf(p1, vv.y, o[1][1]);
            o[1][2] = fmaf(p1, vv.z, o[1][2]); o[1][3] = fmaf(p1, vv.w, o[1][3]);
            o[2][0] = fmaf(p2, vv.x, o[2][0]); o[2][1] = fmaf(p2, vv.y, o[2][1]);
            o[2][2] = fmaf(p2, vv.z, o[2][2]); o[2][3] = fmaf(p2, vv.w, o[2][3]);
            o[3][0] = fmaf(p3, vv.x, o[3][0]); o[3][1] = fmaf(p3, vv.y, o[3][1]);
            o[3][2] = fmaf(p3, vv.z, o[3][2]); o[3][3] = fmaf(p3, vv.w, o[3][3]);
        }
        __syncthreads();
    }

    #pragma unroll
    for (int i = 0; i < 4; i++) {
        const float inv = 1.0f / lreg[i];
        float4 r4;
        r4.x = o[i][0] * inv; r4.y = o[i][1] * inv;
        r4.z = o[i][2] * inv; r4.w = o[i][3] * inv;
        *(float4*)&out[(size_t)(row0 + r0 + i) * D_ + colh + c0o] = r4;
    }
}

// ---------------- launch ------------------------------------------------------
extern "C" void kernel_launch(void* const* d_in, const int* in_sizes, int n_in,
                              void* d_out, int out_size) {
    const float* x     = (const float*)d_in[0];
    const unsigned char* pmask = (const unsigned char*)d_in[1];
    const float* wq = (const float*)d_in[2];
    const float* bq = (const float*)d_in[3];
    const float* wk = (const float*)d_in[4];
    const float* bk = (const float*)d_in[5];
    const float* wv = (const float*)d_in[6];
    const float* bv = (const float*)d_in[7];
    const float* wo = (const float*)d_in[8];
    const float* bo = (const float*)d_in[9];
    const float* w1 = (const float*)d_in[10];
    const float* b1 = (const float*)d_in[11];
    const float* w2 = (const float*)d_in[12];
    const float* b2 = (const float*)d_in[13];
    const float* ln1w = (const float*)d_in[14];
    const float* ln1b = (const float*)d_in[15];
    const float* ln2w = (const float*)d_in[16];
    const float* ln2b = (const float*)d_in[17];
    const float* freqs = (const float*)d_in[18];
    float* out = (float*)d_out;

    float *ph, *pq, *pk, *pv, *patt, *pff;
    cudaGetSymbolAddress((void**)&ph,   g_h);
    cudaGetSymbolAddress((void**)&pq,   g_q);
    cudaGetSymbolAddress((void**)&pk,   g_k);
    cudaGetSymbolAddress((void**)&pv,   g_v);
    cudaGetSymbolAddress((void**)&patt, g_att);
    cudaGetSymbolAddress((void**)&pff,  g_ff);

    cudaFuncSetAttribute(gemm_u<0>, cudaFuncAttributeMaxDynamicSharedMemorySize, GEMM_DYN_SMEM);
    cudaFuncSetAttribute(gemm_u<1>, cudaFuncAttributeMaxDynamicSharedMemorySize, GEMM_DYN_SMEM);
    cudaFuncSetAttribute(gemm_u<2>, cudaFuncAttributeMaxDynamicSharedMemorySize, GEMM_DYN_SMEM);
    cudaFuncSetAttribute(gemm_u<3>, cudaFuncAttributeMaxDynamicSharedMemorySize, GEMM_DYN_SMEM);

    const dim3 gD(D_ / 128, M_ / 128);     // (6, 64)
    const dim3 gF(FF_ / 128, M_ / 128);    // (24, 64)

    // LN1
    ln_kernel<<<M_, 256>>>(x, ln1w, ln1b, ph);
    // QKV projections
    gemm_u<1><<<gD, 256, GEMM_DYN_SMEM>>>(ph, wq, bq, nullptr, pq, M_, D_, D_);
    gemm_u<0><<<gD, 256, GEMM_DYN_SMEM>>>(ph, wk, bk, nullptr, pk, M_, D_, D_);
    gemm_u<0><<<gD, 256, GEMM_DYN_SMEM>>>(ph, wv, bv, nullptr, pv, M_, D_, D_);
    // RoPE on q and k
    const int npairs = M_ * (D_ / 2);
    rope_kernel<<<(npairs + 255) / 256, 256>>>(pq, freqs, npairs);
    rope_kernel<<<(npairs + 255) / 256, 256>>>(pk, freqs, npairs);
    // attention
    attn_kernel<<<dim3(N_ / 64, B_ * H_), 256>>>(pq, pk, pv, pmask, patt);
    // O projection + residual (x) -> d_out
    gemm_u<3><<<gD, 256, GEMM_DYN_SMEM>>>(patt, wo, bo, x, out, M_, D_, D_);
    // LN2 (reuse g_h)
    ln_kernel<<<M_, 256>>>(out, ln2w, ln2b, ph);
    // FFN1 with exact GELU
    gemm_u<2><<<gF, 256, GEMM_DYN_SMEM>>>(ph, w1, b1, nullptr, pff, M_, FF_, D_);
    // FFN2 + residual (d_out) -> d_out
    gemm_u<3><<<gD, 256, GEMM_DYN_SMEM>>>(pff, w2, b2, out, out, M_, D_, FF_);
}

// round 7
// speedup vs baseline: 3.4677x; 1.6707x over previous
#include <cuda_runtime.h>
#include <math.h>
#include <stdint.h>

#define D_  768
#define H_  12
#define HD_ 64
#define FF_ 3072
#define B_  8
#define N_  1024
#define M_  (B_*N_)          // 8192 rows
#define SCALING_ 0.125f      // HD^-0.5
#define EPS_ 1e-5f

// tcgen05 availability: only on arch-specific / family-specific compilation passes.
#if defined(__CUDA_ARCH_FEAT_SM103_ALL) || defined(__CUDA_ARCH_FEAT_SM100_ALL) || \
    defined(__CUDA_ARCH_SPECIFIC__) || defined(__CUDA_ARCH_FAMILY_SPECIFIC__)
#define TC_OK 1
#else
#define TC_OK 0
#endif

// ---------------- scratch (static device globals; no allocation) -------------
__device__ float g_h  [M_*D_];
__device__ float g_q  [M_*D_];
__device__ float g_k  [M_*D_];
__device__ float g_v  [M_*D_];
__device__ float g_att[M_*D_];
__device__ float g_ff [M_*FF_];

// ---------------- common helpers ---------------------------------------------
__device__ __forceinline__ unsigned f2tf32(float f) {
    unsigned r;
    asm("cvt.rna.tf32.f32 %0, %1;" : "=r"(r) : "f"(f));
    return r;
}

#if TC_OK
__device__ __forceinline__ uint32_t smem_u32(const void* p) {
    uint32_t a;
    asm("{ .reg .u64 t; cvta.to.shared.u64 t, %1; cvt.u32.u64 %0, t; }" : "=r"(a) : "l"(p));
    return a;
}
__device__ __forceinline__ uint32_t elect_one() {
    uint32_t p;
    asm volatile("{ .reg .pred p; elect.sync _|p, 0xFFFFFFFF; selp.b32 %0, 1, 0, p; }" : "=r"(p));
    return p;
}
#define TC_ALLOC(smem_addr, n) \
    asm volatile("tcgen05.alloc.cta_group::1.sync.aligned.shared::cta.b32 [%0], %1;" \
                 :: "r"(smem_addr), "r"((uint32_t)(n)) : "memory")
#define TC_RELINQ() \
    asm volatile("tcgen05.relinquish_alloc_permit.cta_group::1.sync.aligned;")
#define TC_DEALLOC(tmem, n) \
    asm volatile("tcgen05.dealloc.cta_group::1.sync.aligned.b32 %0, %1;" :: "r"(tmem), "r"((uint32_t)(n)))
#define TC_COMMIT(mbar) \
    asm volatile("tcgen05.commit.cta_group::1.mbarrier::arrive::one.shared::cluster.b64 [%0];" \
                 :: "r"(mbar) : "memory")
#define TC_FENCE_AFTER()  asm volatile("tcgen05.fence::after_thread_sync;" ::: "memory")
#define FENCE_ASYNC_SH()  asm volatile("fence.proxy.async.shared::cta;" ::: "memory")
#define MBAR_INIT(mbar, cnt) \
    asm volatile("mbarrier.init.shared.b64 [%0], %1;" :: "r"(mbar), "r"((uint32_t)(cnt)) : "memory")
#define MBAR_WAIT(mbar, ph) do {                                                  \
    asm volatile("{\n\t.reg .pred P1;\n\t"                                        \
        "WL_%=:\n\t"                                                              \
        "mbarrier.try_wait.parity.acquire.cta.shared::cta.b64 P1, [%0], %1, 0x989680;\n\t" \
        "@P1 bra.uni WD_%=;\n\t"                                                  \
        "bra.uni WL_%=;\n\t"                                                      \
        "WD_%=:\n\t}"                                                             \
        :: "r"(mbar), "r"((uint32_t)(ph)) : "memory");                            \
} while (0)
#define TC_LD_X32(r, tmem) \
    asm volatile( \
        "tcgen05.ld.sync.aligned.32x32b.x32.b32 " \
        "{%0, %1, %2, %3, %4, %5, %6, %7, " \
        " %8, %9, %10, %11, %12, %13, %14, %15, " \
        " %16, %17, %18, %19, %20, %21, %22, %23, " \
        " %24, %25, %26, %27, %28, %29, %30, %31}, [%32];" \
        : "=r"((r)[0]),  "=r"((r)[1]),  "=r"((r)[2]),  "=r"((r)[3]), \
          "=r"((r)[4]),  "=r"((r)[5]),  "=r"((r)[6]),  "=r"((r)[7]), \
          "=r"((r)[8]),  "=r"((r)[9]),  "=r"((r)[10]), "=r"((r)[11]), \
          "=r"((r)[12]), "=r"((r)[13]), "=r"((r)[14]), "=r"((r)[15]), \
          "=r"((r)[16]), "=r"((r)[17]), "=r"((r)[18]), "=r"((r)[19]), \
          "=r"((r)[20]), "=r"((r)[21]), "=r"((r)[22]), "=r"((r)[23]), \
          "=r"((r)[24]), "=r"((r)[25]), "=r"((r)[26]), "=r"((r)[27]), \
          "=r"((r)[28]), "=r"((r)[29]), "=r"((r)[30]), "=r"((r)[31]) \
        : "r"(tmem))
#define TC_WAIT_LD() asm volatile("tcgen05.wait::ld.sync.aligned;" ::: "memory")

__device__ __forceinline__ void tc_mma_tf32_ss(uint32_t d, uint64_t ad, uint64_t bd,
                                               uint32_t idesc, bool acc) {
    uint32_t e = acc ? 1u : 0u;
    asm volatile(
        "{\n\t.reg .pred p;\n\tsetp.ne.u32 p, %4, 0;\n\t"
        "tcgen05.mma.cta_group::1.kind::tf32 [%0], %1, %2, %3, {%5,%5,%5,%5}, p;\n\t}"
        :: "r"(d), "l"(ad), "l"(bd), "r"(idesc), "r"(e), "r"(0u) : "memory");
}
// SW128 K-major smem descriptor: layout=2, version=1, SBO=64, LBO=1
__device__ __forceinline__ uint64_t mk_desc(uint32_t addr) {
    const uint64_t base = (uint64_t(2) << 61) | (uint64_t(1) << 46)
                        | (uint64_t(64) << 32) | (uint64_t(1) << 16);
    return base | ((uint64_t)(addr >> 4) & 0x3FFF);
}
#define SWZ128(b) ((b) ^ (((b) >> 3) & 0x70))
// idesc: cfmt=F32(1)<<4, a=TF32(2)<<7, b=TF32(2)<<10, N=128 ->16<<17, M=128 ->8<<24
#define TC_IDESC ((1u<<4)|(2u<<7)|(2u<<10)|(16u<<17)|(8u<<24))
#endif  // TC_OK

__device__ __forceinline__ void mma_tf32(float& c0, float& c1, float& c2, float& c3,
                                         unsigned a0, unsigned a1, unsigned a2, unsigned a3,
                                         unsigned b0, unsigned b1) {
    asm volatile(
        "mma.sync.aligned.m16n8k8.row.col.f32.tf32.tf32.f32 "
        "{%0,%1,%2,%3}, {%4,%5,%6,%7}, {%8,%9}, {%0,%1,%2,%3};"
        : "+f"(c0), "+f"(c1), "+f"(c2), "+f"(c3)
        : "r"(a0), "r"(a1), "r"(a2), "r"(a3), "r"(b0), "r"(b1));
}

// ---------------- LayerNorm: one block per row -------------------------------
__global__ __launch_bounds__(256)
void ln_kernel(const float* __restrict__ x, const float* __restrict__ w,
               const float* __restrict__ b, float* __restrict__ out) {
    const int row = blockIdx.x;
    const int tid = threadIdx.x;
    const float* xr = x + (size_t)row * D_;
    float v[3];
    float s = 0.f;
    #pragma unroll
    for (int i = 0; i < 3; i++) { v[i] = xr[tid + i*256]; s += v[i]; }

    __shared__ float red[8];
    __shared__ float bc[2];
    #pragma unroll
    for (int o = 16; o; o >>= 1) s += __shfl_xor_sync(0xffffffffu, s, o);
    if ((tid & 31) == 0) red[tid >> 5] = s;
    __syncthreads();
    if (tid == 0) {
        float t = 0.f;
        #pragma unroll
        for (int i = 0; i < 8; i++) t += red[i];
        bc[0] = t * (1.0f / D_);
    }
    __syncthreads();
    const float mu = bc[0];

    float s2 = 0.f;
    #pragma unroll
    for (int i = 0; i < 3; i++) { float d = v[i] - mu; s2 += d * d; }
    #pragma unroll
    for (int o = 16; o; o >>= 1) s2 += __shfl_xor_sync(0xffffffffu, s2, o);
    if ((tid & 31) == 0) red[tid >> 5] = s2;
    __syncthreads();
    if (tid == 0) {
        float t = 0.f;
        #pragma unroll
        for (int i = 0; i < 8; i++) t += red[i];
        bc[1] = rsqrtf(t * (1.0f / D_) + EPS_);
    }
    __syncthreads();
    const float rstd = bc[1];

    float* orow = out + (size_t)row * D_;
    #pragma unroll
    for (int i = 0; i < 3; i++) {
        int c = tid + i*256;
        orow[c] = (v[i] - mu) * rstd * w[c] + b[c];
    }
}

// ---------------- unified tf32 NT GEMM (unchanged from R6) --------------------
#define STAGE_BYTES 16384
#define GEMM_DYN_SMEM (4*STAGE_BYTES + 1024)

template<int EP>
__global__ __launch_bounds__(256, 2)
void gemm_u(const float* __restrict__ A, const float* __restrict__ W,
            const float* __restrict__ bias, const float* __restrict__ res,
            float* __restrict__ C, int M, int N, int K) {
#if TC_OK
    extern __shared__ char dsm[];
    __shared__ uint32_t tmem_ptr_s[1];
    __shared__ __align__(8) uint64_t mbar_s[2];

    const int tid  = threadIdx.x;
    const int warp = tid >> 5;
    const int lane = tid & 31;
    const int m0 = blockIdx.y << 7, n0 = blockIdx.x << 7;

    uint32_t rawb = smem_u32(dsm);
    uint32_t ab   = (rawb + 1023u) & ~1023u;
    char* sbase = dsm + (ab - rawb);
    char* sA[2] = { sbase,                 sbase + STAGE_BYTES };
    char* sB[2] = { sbase + 2*STAGE_BYTES, sbase + 3*STAGE_BYTES };
    const uint32_t aAddr[2] = { ab, ab + STAGE_BYTES };
    const uint32_t bAddr[2] = { ab + 2*STAGE_BYTES, ab + 3*STAGE_BYTES };
    const uint32_t mbar0 = smem_u32(&mbar_s[0]);
    const uint32_t mbar1 = smem_u32(&mbar_s[1]);

    if (warp == 0) {
        TC_ALLOC(smem_u32(tmem_ptr_s), 128);
        TC_RELINQ();
    }
    if (tid == 0) { MBAR_INIT(mbar0, 1); MBAR_INIT(mbar1, 1); }
    __syncthreads();
    uint32_t tmem;
    asm volatile("ld.shared.b32 %0, [%1];" : "=r"(tmem) : "r"(smem_u32(tmem_ptr_s)));

    const int prow = tid >> 3;
    const int psub = tid & 7;

    const int nst = K >> 5;
    for (int s = 0; s < nst; s++) {
        const int b = s & 1;
        if (s >= 2) MBAR_WAIT(b ? mbar1 : mbar0, ((s - 2) >> 1) & 1);
        const int k0 = s << 5;
        #pragma unroll
        for (int p = 0; p < 4; p++) {
            const int r = prow + (p << 5);
            const float4 av = *(const float4*)(A + (size_t)(m0 + r) * K + k0 + (psub << 2));
            const float4 wv = *(const float4*)(W + (size_t)(n0 + r) * K + k0 + (psub << 2));
            const uint32_t off = SWZ128((r << 7) | (psub << 4));
            uint4 at, wt;
            at.x = f2tf32(av.x); at.y = f2tf32(av.y); at.z = f2tf32(av.z); at.w = f2tf32(av.w);
            wt.x = f2tf32(wv.x); wt.y = f2tf32(wv.y); wt.z = f2tf32(wv.z); wt.w = f2tf32(wv.w);
            *(uint4*)(sA[b] + off) = at;
            *(uint4*)(sB[b] + off) = wt;
        }
        FENCE_ASYNC_SH();
        __syncthreads();
        if (warp == 0 && elect_one()) {
            const uint64_t ad = mk_desc(aAddr[b]);
            const uint64_t bd = mk_desc(bAddr[b]);
            #pragma unroll
            for (int k = 0; k < 4; k++)
                tc_mma_tf32_ss(tmem, ad + k*2, bd + k*2, TC_IDESC, (s > 0) || (k > 0));
            TC_COMMIT(b ? mbar1 : mbar0);
        }
        __syncthreads();
    }

    const int ls = nst - 1;
    MBAR_WAIT((ls & 1) ? mbar1 : mbar0, (ls >> 1) & 1);
    TC_FENCE_AFTER();

    uint32_t dr[64];
    const int cb = (warp >> 2) << 6;
    TC_LD_X32(dr,      tmem + cb);
    TC_LD_X32(dr + 32, tmem + cb + 32);
    TC_WAIT_LD();

    const int r  = m0 + ((warp & 3) << 5) + lane;
    const int cg = n0 + cb;
    float* crow = C + (size_t)r * N + cg;
    const float* rrow = (EP == 3) ? (res + (size_t)r * N + cg) : nullptr;
    #pragma unroll
    for (int j4 = 0; j4 < 16; j4++) {
        float4 bv = *(const float4*)(bias + cg + (j4 << 2));
        float4 o;
        o.x = __uint_as_float(dr[j4*4+0]) + bv.x;
        o.y = __uint_as_float(dr[j4*4+1]) + bv.y;
        o.z = __uint_as_float(dr[j4*4+2]) + bv.z;
        o.w = __uint_as_float(dr[j4*4+3]) + bv.w;
        if (EP == 1) { o.x *= SCALING_; o.y *= SCALING_; o.z *= SCALING_; o.w *= SCALING_; }
        if (EP == 2) {
            o.x = 0.5f * o.x * (1.0f + erff(o.x * 0.70710678118654752f));
            o.y = 0.5f * o.y * (1.0f + erff(o.y * 0.70710678118654752f));
            o.z = 0.5f * o.z * (1.0f + erff(o.z * 0.70710678118654752f));
            o.w = 0.5f * o.w * (1.0f + erff(o.w * 0.70710678118654752f));
        }
        if (EP == 3) {
            float4 rv = *(const float4*)(rrow + (j4 << 2));
            o.x += rv.x; o.y += rv.y; o.z += rv.z; o.w += rv.w;
        }
        *(float4*)(crow + (j4 << 2)) = o;
    }

    __syncthreads();
    if (warp == 0) TC_DEALLOC(tmem, 128);

#else  // fallback: mma.sync path
    extern __shared__ char dsm[];
    typedef unsigned SmemBuf[128][16];
    SmemBuf* As = reinterpret_cast<SmemBuf*>(dsm);
    SmemBuf* Ws = reinterpret_cast<SmemBuf*>(dsm + 2 * sizeof(SmemBuf));

    const int tid  = threadIdx.x;
    const int lane = tid & 31;
    const int warp = tid >> 5;
    const int wm = (warp >> 2) * 64;
    const int wn = (warp & 3) * 32;
    const int grp = lane >> 2;
    const int qk  = lane & 3;

    const int m0 = blockIdx.y << 7, n0 = blockIdx.x << 7;

    const int ldr = tid >> 2;
    const int sub = tid & 3;
    const float* Ap0 = A + (size_t)(m0 + ldr) * K + (sub << 2);
    const float* Ap1 = A + (size_t)(m0 + ldr + 64) * K + (sub << 2);
    const float* Wp0 = W + (size_t)(n0 + ldr) * K + (sub << 2);
    const float* Wp1 = W + (size_t)(n0 + ldr + 64) * K + (sub << 2);
    const int sw0 = ((ldr >> 1) & 3);
    const int sw1 = (((ldr + 64) >> 1) & 3);

    float acc[4][4][4];
    #pragma unroll
    for (int i = 0; i < 4; i++)
        #pragma unroll
        for (int j = 0; j < 4; j++)
            #pragma unroll
            for (int f = 0; f < 4; f++) acc[i][j][f] = 0.f;

    const int ntiles = K >> 4;

    #define STORE_TILE(buf, a0v, a1v, w0v, w1v)                                              \
        do {                                                                                  \
            As[buf][ldr   ][((0^sw0)<<2)+sub]=f2tf32(a0v.x); As[buf][ldr   ][((1^sw0)<<2)+sub]=f2tf32(a0v.y); \
            As[buf][ldr   ][((2^sw0)<<2)+sub]=f2tf32(a0v.z); As[buf][ldr   ][((3^sw0)<<2)+sub]=f2tf32(a0v.w); \
            As[buf][ldr+64][((0^sw1)<<2)+sub]=f2tf32(a1v.x); As[buf][ldr+64][((1^sw1)<<2)+sub]=f2tf32(a1v.y); \
            As[buf][ldr+64][((2^sw1)<<2)+sub]=f2tf32(a1v.z); As[buf][ldr+64][((3^sw1)<<2)+sub]=f2tf32(a1v.w); \
            Ws[buf][ldr   ][((0^sw0)<<2)+sub]=f2tf32(w0v.x); Ws[buf][ldr   ][((1^sw0)<<2)+sub]=f2tf32(w0v.y); \
            Ws[buf][ldr   ][((2^sw0)<<2)+sub]=f2tf32(w0v.z); Ws[buf][ldr   ][((3^sw0)<<2)+sub]=f2tf32(w0v.w); \
            Ws[buf][ldr+64][((0^sw1)<<2)+sub]=f2tf32(w1v.x); Ws[buf][ldr+64][((1^sw1)<<2)+sub]=f2tf32(w1v.y); \
            Ws[buf][ldr+64][((2^sw1)<<2)+sub]=f2tf32(w1v.z); Ws[buf][ldr+64][((3^sw1)<<2)+sub]=f2tf32(w1v.w); \
        } while (0)

    {
        float4 a0 = *(const float4*)(Ap0);
        float4 a1 = *(const float4*)(Ap1);
        float4 w0 = *(const float4*)(Wp0);
        float4 w1 = *(const float4*)(Wp1);
        STORE_TILE(0, a0, a1, w0, w1);
    }
    __syncthreads();

    for (int it = 0; it < ntiles; it++) {
        const int cur = it & 1, nxt = cur ^ 1;
        float4 a0, a1, w0, w1;
        const bool have_next = (it + 1) < ntiles;
        if (have_next) {
            const int ko = (it + 1) << 4;
            a0 = *(const float4*)(Ap0 + ko);
            a1 = *(const float4*)(Ap1 + ko);
            w0 = *(const float4*)(Wp0 + ko);
            w1 = *(const float4*)(Wp1 + ko);
        }

        uint4 Bv[4];
        #pragma unroll
        for (int ni = 0; ni < 4; ni++) {
            const int rn = wn + (ni << 3) + grp;
            Bv[ni] = *(const uint4*)&Ws[cur][rn][((qk ^ ((rn >> 1) & 3)) << 2)];
        }
        #pragma unroll
        for (int mi = 0; mi < 4; mi++) {
            const int rl = wm + (mi << 4) + grp;
            const int rh = rl + 8;
            const uint4 Alo = *(const uint4*)&As[cur][rl][((qk ^ ((rl >> 1) & 3)) << 2)];
            const uint4 Ahi = *(const uint4*)&As[cur][rh][((qk ^ ((rh >> 1) & 3)) << 2)];
            #pragma unroll
            for (int ni = 0; ni < 4; ni++) {
                mma_tf32(acc[mi][ni][0], acc[mi][ni][1], acc[mi][ni][2], acc[mi][ni][3],
                         Alo.x, Ahi.x, Alo.y, Ahi.y, Bv[ni].x, Bv[ni].y);
                mma_tf32(acc[mi][ni][0], acc[mi][ni][1], acc[mi][ni][2], acc[mi][ni][3],
                         Alo.z, Ahi.z, Alo.w, Ahi.w, Bv[ni].z, Bv[ni].w);
            }
        }

        if (have_next) {
            STORE_TILE(nxt, a0, a1, w0, w1);
        }
        __syncthreads();
    }
    #undef STORE_TILE

    #pragma unroll
    for (int mi = 0; mi < 4; mi++) {
        #pragma unroll
        for (int ni = 0; ni < 4; ni++) {
            #pragma unroll
            for (int f = 0; f < 4; f++) {
                const int r = m0 + wm + (mi << 4) + grp + ((f >> 1) << 3);
                const int c = n0 + wn + (ni << 3) + (qk << 1) + (f & 1);
                float val = acc[mi][ni][f] + bias[c];
                if (EP == 1) val *= SCALING_;
                if (EP == 2) val = 0.5f * val * (1.0f + erff(val * 0.70710678118654752f));
                if (EP == 3) val += res[(size_t)r * N + c];
                C[(size_t)r * N + c] = val;
            }
        }
    }
#endif
}

// ---------------- RoPE (interleaved pairs), in-place -------------------------
__global__ void rope_kernel(float* __restrict__ t, const float* __restrict__ freqs, int npairs) {
    int idx = blockIdx.x * blockDim.x + threadIdx.x;
    if (idx >= npairs) return;
    const int row = idx / (D_ / 2);
    const int p   = idx - row * (D_ / 2);
    const int i   = p & 31;
    const int n   = row & (N_ - 1);
    const float ang = (float)n * freqs[i];
    const float c = cosf(ang), s = sinf(ang);
    float* base = t + (size_t)row * D_ + p * 2;
    const float x0 = base[0], x1 = base[1];
    base[0] = x0 * c - x1 * s;
    base[1] = x1 * c + x0 * s;
}

// ---------------- flash attention, tf32 mma.sync, BQ=128 BK=64 ---------------
// Smem chunk-plane layout: X[plane c][row][16 words], plane covers k16-chunk c.
// Within a chunk, element k lives at quad (k&3)^((row>>1)&3), word k>>2.
// Consumer LDS.128 at quad qk^((row>>1)&3) -> k = {qk,qk+4,qk+8,qk+12}.
#define ATTN_SMEM (16384 + 16384 + 32768 + 64)
__global__ __launch_bounds__(256, 2)
void attn_tc(const float* __restrict__ q, const float* __restrict__ k,
             const float* __restrict__ v, const unsigned char* __restrict__ pm,
             float* __restrict__ out) {
    extern __shared__ char asmem[];
    unsigned* Ks = (unsigned*)asmem;               // [4][64][16]  keys x d
    unsigned* Vt = (unsigned*)(asmem + 16384);     // [4][64][16]  dims x keys
    unsigned* Ps = (unsigned*)(asmem + 32768);     // [4][128][16] qrows x keys
    unsigned char* Ms = (unsigned char*)(asmem + 65536);

    const int tid = threadIdx.x, warp = tid >> 5, lane = tid & 31;
    const int grp = lane >> 2, qk = lane & 3;
    const int qt = blockIdx.x, bh = blockIdx.y;
    const int b = bh / H_, h = bh - b * H_;
    const int row0 = b * N_ + qt * 128;
    const int colh = h * HD_;
    const int wr = warp << 4;            // warp's first local q-row
    const int rl0 = wr + grp;            // local row (first)
    const int rl1 = rl0 + 8;
    const int r0 = row0 + rl0;           // global rows

    // Q A-fragments, resident (8 k8-steps x 4 regs)
    unsigned aq[8][4];
    {
        const float* q0 = q + (size_t)r0 * D_ + colh;
        const float* q1 = q0 + (size_t)8 * D_;
        #pragma unroll
        for (int s = 0; s < 8; s++) {
            aq[s][0] = f2tf32(q0[s*8 + qk]);
            aq[s][1] = f2tf32(q1[s*8 + qk]);
            aq[s][2] = f2tf32(q0[s*8 + qk + 4]);
            aq[s][3] = f2tf32(q1[s*8 + qk + 4]);
        }
    }

    float o_[8][4];
    #pragma unroll
    for (int nt = 0; nt < 8; nt++) { o_[nt][0]=0.f; o_[nt][1]=0.f; o_[nt][2]=0.f; o_[nt][3]=0.f; }
    float m0 = -3.0e38f, m1 = -3.0e38f, l0 = 0.f, l1 = 0.f;

    // producer mapping: key = tid>>2 (0..63), lq = tid&3
    const int lkey = tid >> 2, lq = tid & 3;
    const int swk = (lkey >> 1) & 3;
    const int vpl = lkey >> 4, vkk = lkey & 15;
    const int swp0 = (rl0 >> 1) & 3, swp1 = (rl1 >> 1) & 3;

    for (int kt = 0; kt < N_; kt += 64) {
        __syncthreads();   // previous iter's consumers done
        {
            const size_t gbase = (size_t)(b * N_ + kt + lkey) * D_ + colh;
            #pragma unroll
            for (int c = 0; c < 4; c++) {
                const float4 k4 = *(const float4*)(k + gbase + 16*c + 4*lq);
                const float4 v4 = *(const float4*)(v + gbase + 16*c + 4*lq);
                unsigned* kp = Ks + (c << 10) + (lkey << 4);
                kp[((0^swk)<<2)+lq] = f2tf32(k4.x);
                kp[((1^swk)<<2)+lq] = f2tf32(k4.y);
                kp[((2^swk)<<2)+lq] = f2tf32(k4.z);
                kp[((3^swk)<<2)+lq] = f2tf32(k4.w);
                const float vv[4] = {v4.x, v4.y, v4.z, v4.w};
                #pragma unroll
                for (int i = 0; i < 4; i++) {
                    const int d = 16*c + 4*lq + i;
                    const int quad = (vkk & 3) ^ ((d >> 1) & 3);
                    Vt[(vpl << 10) + (d << 4) + (quad << 2) + (vkk >> 2)] = f2tf32(vv[i]);
                }
            }
            if (tid < 64) Ms[tid] = pm[b * N_ + kt + tid];
        }
        __syncthreads();

        // S = Q K^T  (per warp: 16 rows x 64 keys)
        float s_[8][4];
        #pragma unroll
        for (int nt = 0; nt < 8; nt++) { s_[nt][0]=0.f; s_[nt][1]=0.f; s_[nt][2]=0.f; s_[nt][3]=0.f; }
        #pragma unroll
        for (int c = 0; c < 4; c++) {
            #pragma unroll
            for (int nt = 0; nt < 8; nt++) {
                const int rn = (nt << 3) + grp;
                const uint4 Bv = *(const uint4*)(Ks + (c << 10) + (rn << 4)
                                                 + ((qk ^ ((rn >> 1) & 3)) << 2));
                mma_tf32(s_[nt][0], s_[nt][1], s_[nt][2], s_[nt][3],
                         aq[2*c][0], aq[2*c][1], aq[2*c][2], aq[2*c][3], Bv.x, Bv.y);
                mma_tf32(s_[nt][0], s_[nt][1], s_[nt][2], s_[nt][3],
                         aq[2*c+1][0], aq[2*c+1][1], aq[2*c+1][2], aq[2*c+1][3], Bv.z, Bv.w);
            }
        }

        // mask + scale + row max
        float mx0 = -3.0e38f, mx1 = -3.0e38f;
        #pragma unroll
        for (int nt = 0; nt < 8; nt++) {
            const int c0 = (nt << 3) + (qk << 1);
            const bool k0m = Ms[c0] != 0, k1m = Ms[c0 + 1] != 0;
            s_[nt][0] = k0m ? -3.0e38f : s_[nt][0] * 0.125f;
            s_[nt][1] = k1m ? -3.0e38f : s_[nt][1] * 0.125f;
            s_[nt][2] = k0m ? -3.0e38f : s_[nt][2] * 0.125f;
            s_[nt][3] = k1m ? -3.0e38f : s_[nt][3] * 0.125f;
            mx0 = fmaxf(mx0, fmaxf(s_[nt][0], s_[nt][1]));
            mx1 = fmaxf(mx1, fmaxf(s_[nt][2], s_[nt][3]));
        }
        mx0 = fmaxf(mx0, __shfl_xor_sync(0xffffffffu, mx0, 1));
        mx0 = fmaxf(mx0, __shfl_xor_sync(0xffffffffu, mx0, 2));
        mx1 = fmaxf(mx1, __shfl_xor_sync(0xffffffffu, mx1, 1));
        mx1 = fmaxf(mx1, __shfl_xor_sync(0xffffffffu, mx1, 2));

        const float mn0 = fmaxf(m0, mx0), mn1 = fmaxf(m1, mx1);
        const float al0 = __expf(m0 - mn0), al1 = __expf(m1 - mn1);
        m0 = mn0; m1 = mn1;
        float rs0 = 0.f, rs1 = 0.f;
        #pragma unroll
        for (int nt = 0; nt < 8; nt++) {
            s_[nt][0] = __expf(s_[nt][0] - mn0);
            s_[nt][1] = __expf(s_[nt][1] - mn0);
            s_[nt][2] = __expf(s_[nt][2] - mn1);
            s_[nt][3] = __expf(s_[nt][3] - mn1);
            rs0 += s_[nt][0] + s_[nt][1];
            rs1 += s_[nt][2] + s_[nt][3];
            o_[nt][0] *= al0; o_[nt][1] *= al0;
            o_[nt][2] *= al1; o_[nt][3] *= al1;
        }
        rs0 += __shfl_xor_sync(0xffffffffu, rs0, 1);
        rs0 += __shfl_xor_sync(0xffffffffu, rs0, 2);
        rs1 += __shfl_xor_sync(0xffffffffu, rs1, 1);
        rs1 += __shfl_xor_sync(0xffffffffu, rs1, 2);
        l0 = l0 * al0 + rs0;
        l1 = l1 * al1 + rs1;

        // store P into chunk-plane smem
        #pragma unroll
        for (int nt = 0; nt < 8; nt++) {
            #pragma unroll
            for (int i2 = 0; i2 < 2; i2++) {
                const int ck = (nt << 3) + (qk << 1) + i2;
                const int pl = ck >> 4, kk = ck & 15;
                const int w_ = kk >> 2;
                Ps[(pl << 11) + (rl0 << 4) + ((((kk & 3) ^ swp0)) << 2) + w_] = f2tf32(s_[nt][i2]);
                Ps[(pl << 11) + (rl1 << 4) + ((((kk & 3) ^ swp1)) << 2) + w_] = f2tf32(s_[nt][2 + i2]);
            }
        }
        __syncthreads();

        // O += P V
        #pragma unroll
        for (int c = 0; c < 4; c++) {
            const uint4 Alo = *(const uint4*)(Ps + (c << 11) + (rl0 << 4) + ((qk ^ swp0) << 2));
            const uint4 Ahi = *(const uint4*)(Ps + (c << 11) + (rl1 << 4) + ((qk ^ swp1) << 2));
            #pragma unroll
            for (int nt = 0; nt < 8; nt++) {
                const int rn = (nt << 3) + grp;
                const uint4 Bv = *(const uint4*)(Vt + (c << 10) + (rn << 4)
                                                 + ((qk ^ ((rn >> 1) & 3)) << 2));
                mma_tf32(o_[nt][0], o_[nt][1], o_[nt][2], o_[nt][3],
                         Alo.x, Ahi.x, Alo.y, Ahi.y, Bv.x, Bv.y);
                mma_tf32(o_[nt][0], o_[nt][1], o_[nt][2], o_[nt][3],
                         Alo.z, Ahi.z, Alo.w, Ahi.w, Bv.z, Bv.w);
            }
        }
    }

    const float inv0 = 1.0f / l0, inv1 = 1.0f / l1;
    float* out0 = out + (size_t)r0 * D_ + colh;
    float* out1 = out0 + (size_t)8 * D_;
    #pragma unroll
    for (int nt = 0; nt < 8; nt++) {
        const int c0 = (nt << 3) + (qk << 1);
        out0[c0]     = o_[nt][0] * inv0;
        out0[c0 + 1] = o_[nt][1] * inv0;
        out1[c0]     = o_[nt][2] * inv1;
        out1[c0 + 1] = o_[nt][3] * inv1;
    }
}

// ---------------- launch ------------------------------------------------------
extern "C" void kernel_launch(void* const* d_in, const int* in_sizes, int n_in,
                              void* d_out, int out_size) {
    const float* x     = (const float*)d_in[0];
    const unsigned char* pmask = (const unsigned char*)d_in[1];
    const float* wq = (const float*)d_in[2];
    const float* bq = (const float*)d_in[3];
    const float* wk = (const float*)d_in[4];
    const float* bk = (const float*)d_in[5];
    const float* wv = (const float*)d_in[6];
    const float* bv = (const float*)d_in[7];
    const float* wo = (const float*)d_in[8];
    const float* bo = (const float*)d_in[9];
    const float* w1 = (const float*)d_in[10];
    const float* b1 = (const float*)d_in[11];
    const float* w2 = (const float*)d_in[12];
    const float* b2 = (const float*)d_in[13];
    const float* ln1w = (const float*)d_in[14];
    const float* ln1b = (const float*)d_in[15];
    const float* ln2w = (const float*)d_in[16];
    const float* ln2b = (const float*)d_in[17];
    const float* freqs = (const float*)d_in[18];
    float* out = (float*)d_out;

    float *ph, *pq, *pk, *pv, *patt, *pff;
    cudaGetSymbolAddress((void**)&ph,   g_h);
    cudaGetSymbolAddress((void**)&pq,   g_q);
    cudaGetSymbolAddress((void**)&pk,   g_k);
    cudaGetSymbolAddress((void**)&pv,   g_v);
    cudaGetSymbolAddress((void**)&patt, g_att);
    cudaGetSymbolAddress((void**)&pff,  g_ff);

    cudaFuncSetAttribute(gemm_u<0>, cudaFuncAttributeMaxDynamicSharedMemorySize, GEMM_DYN_SMEM);
    cudaFuncSetAttribute(gemm_u<1>, cudaFuncAttributeMaxDynamicSharedMemorySize, GEMM_DYN_SMEM);
    cudaFuncSetAttribute(gemm_u<2>, cudaFuncAttributeMaxDynamicSharedMemorySize, GEMM_DYN_SMEM);
    cudaFuncSetAttribute(gemm_u<3>, cudaFuncAttributeMaxDynamicSharedMemorySize, GEMM_DYN_SMEM);
    cudaFuncSetAttribute(attn_tc,   cudaFuncAttributeMaxDynamicSharedMemorySize, ATTN_SMEM);

    const dim3 gD(D_ / 128, M_ / 128);     // (6, 64)
    const dim3 gF(FF_ / 128, M_ / 128);    // (24, 64)

    // LN1
    ln_kernel<<<M_, 256>>>(x, ln1w, ln1b, ph);
    // QKV projections
    gemm_u<1><<<gD, 256, GEMM_DYN_SMEM>>>(ph, wq, bq, nullptr, pq, M_, D_, D_);
    gemm_u<0><<<gD, 256, GEMM_DYN_SMEM>>>(ph, wk, bk, nullptr, pk, M_, D_, D_);
    gemm_u<0><<<gD, 256, GEMM_DYN_SMEM>>>(ph, wv, bv, nullptr, pv, M_, D_, D_);
    // RoPE on q and k
    const int npairs = M_ * (D_ / 2);
    rope_kernel<<<(npairs + 255) / 256, 256>>>(pq, freqs, npairs);
    rope_kernel<<<(npairs + 255) / 256, 256>>>(pk, freqs, npairs);
    // attention (tf32 tensor cores)
    attn_tc<<<dim3(N_ / 128, B_ * H_), 256, ATTN_SMEM>>>(pq, pk, pv, pmask, patt);
    // O projection + residual (x) -> d_out
    gemm_u<3><<<gD, 256, GEMM_DYN_SMEM>>>(patt, wo, bo, x, out, M_, D_, D_);
    // LN2 (reuse g_h)
    ln_kernel<<<M_, 256>>>(out, ln2w, ln2b, ph);
    // FFN1 with exact GELU
    gemm_u<2><<<gF, 256, GEMM_DYN_SMEM>>>(ph, w1, b1, nullptr, pff, M_, FF_, D_);
    // FFN2 + residual (d_out) -> d_out
    gemm_u<3><<<gD, 256, GEMM_DYN_SMEM>>>(pff, w2, b2, out, out, M_, D_, FF_);
}

// round 9
// speedup vs baseline: 4.0848x; 1.1780x over previous
#include <cuda_runtime.h>
#include <math.h>
#include <stdint.h>

#define D_  768
#define H_  12
#define HD_ 64
#define FF_ 3072
#define B_  8
#define N_  1024
#define M_  (B_*N_)          // 8192 rows
#define SCALING_ 0.125f      // HD^-0.5
#define EPS_ 1e-5f

// tcgen05 availability: only on arch-specific / family-specific compilation passes.
#if defined(__CUDA_ARCH_FEAT_SM103_ALL) || defined(__CUDA_ARCH_FEAT_SM100_ALL) || \
    defined(__CUDA_ARCH_SPECIFIC__) || defined(__CUDA_ARCH_FAMILY_SPECIFIC__)
#define TC_OK 1
#else
#define TC_OK 0
#endif

// ---------------- scratch (static device globals; no allocation) -------------
__device__ float g_h  [M_*D_];
__device__ float g_q  [M_*D_];
__device__ float g_k  [M_*D_];
__device__ float g_v  [M_*D_];
__device__ float g_att[M_*D_];
__device__ float g_ff [M_*FF_];

// ---------------- common helpers ---------------------------------------------
__device__ __forceinline__ unsigned f2tf32(float f) {
    unsigned r;
    asm("cvt.rna.tf32.f32 %0, %1;" : "=r"(r) : "f"(f));
    return r;
}

#if TC_OK
__device__ __forceinline__ uint32_t smem_u32(const void* p) {
    uint32_t a;
    asm("{ .reg .u64 t; cvta.to.shared.u64 t, %1; cvt.u32.u64 %0, t; }" : "=r"(a) : "l"(p));
    return a;
}
__device__ __forceinline__ uint32_t elect_one() {
    uint32_t p;
    asm volatile("{ .reg .pred p; elect.sync _|p, 0xFFFFFFFF; selp.b32 %0, 1, 0, p; }" : "=r"(p));
    return p;
}
#define TC_ALLOC(smem_addr, n) \
    asm volatile("tcgen05.alloc.cta_group::1.sync.aligned.shared::cta.b32 [%0], %1;" \
                 :: "r"(smem_addr), "r"((uint32_t)(n)) : "memory")
#define TC_RELINQ() \
    asm volatile("tcgen05.relinquish_alloc_permit.cta_group::1.sync.aligned;")
#define TC_DEALLOC(tmem, n) \
    asm volatile("tcgen05.dealloc.cta_group::1.sync.aligned.b32 %0, %1;" :: "r"(tmem), "r"((uint32_t)(n)))
#define TC_COMMIT(mbar) \
    asm volatile("tcgen05.commit.cta_group::1.mbarrier::arrive::one.shared::cluster.b64 [%0];" \
                 :: "r"(mbar) : "memory")
#define TC_FENCE_AFTER()  asm volatile("tcgen05.fence::after_thread_sync;" ::: "memory")
#define FENCE_ASYNC_SH()  asm volatile("fence.proxy.async.shared::cta;" ::: "memory")
#define MBAR_INIT(mbar, cnt) \
    asm volatile("mbarrier.init.shared.b64 [%0], %1;" :: "r"(mbar), "r"((uint32_t)(cnt)) : "memory")
#define MBAR_WAIT(mbar, ph) do {                                                  \
    asm volatile("{\n\t.reg .pred P1;\n\t"                                        \
        "WL_%=:\n\t"                                                              \
        "mbarrier.try_wait.parity.acquire.cta.shared::cta.b64 P1, [%0], %1, 0x989680;\n\t" \
        "@P1 bra.uni WD_%=;\n\t"                                                  \
        "bra.uni WL_%=;\n\t"                                                      \
        "WD_%=:\n\t}"                                                             \
        :: "r"(mbar), "r"((uint32_t)(ph)) : "memory");                            \
} while (0)
#define TC_LD_X32(r, tmem) \
    asm volatile( \
        "tcgen05.ld.sync.aligned.32x32b.x32.b32 " \
        "{%0, %1, %2, %3, %4, %5, %6, %7, " \
        " %8, %9, %10, %11, %12, %13, %14, %15, " \
        " %16, %17, %18, %19, %20, %21, %22, %23, " \
        " %24, %25, %26, %27, %28, %29, %30, %31}, [%32];" \
        : "=r"((r)[0]),  "=r"((r)[1]),  "=r"((r)[2]),  "=r"((r)[3]), \
          "=r"((r)[4]),  "=r"((r)[5]),  "=r"((r)[6]),  "=r"((r)[7]), \
          "=r"((r)[8]),  "=r"((r)[9]),  "=r"((r)[10]), "=r"((r)[11]), \
          "=r"((r)[12]), "=r"((r)[13]), "=r"((r)[14]), "=r"((r)[15]), \
          "=r"((r)[16]), "=r"((r)[17]), "=r"((r)[18]), "=r"((r)[19]), \
          "=r"((r)[20]), "=r"((r)[21]), "=r"((r)[22]), "=r"((r)[23]), \
          "=r"((r)[24]), "=r"((r)[25]), "=r"((r)[26]), "=r"((r)[27]), \
          "=r"((r)[28]), "=r"((r)[29]), "=r"((r)[30]), "=r"((r)[31]) \
        : "r"(tmem))
#define TC_WAIT_LD() asm volatile("tcgen05.wait::ld.sync.aligned;" ::: "memory")

__device__ __forceinline__ void tc_mma_tf32_ss(uint32_t d, uint64_t ad, uint64_t bd,
                                               uint32_t idesc, bool acc) {
    uint32_t e = acc ? 1u : 0u;
    asm volatile(
        "{\n\t.reg .pred p;\n\tsetp.ne.u32 p, %4, 0;\n\t"
        "tcgen05.mma.cta_group::1.kind::tf32 [%0], %1, %2, %3, {%5,%5,%5,%5}, p;\n\t}"
        :: "r"(d), "l"(ad), "l"(bd), "r"(idesc), "r"(e), "r"(0u) : "memory");
}
// SW128 K-major smem descriptor: layout=2, version=1, SBO=64, LBO=1
__device__ __forceinline__ uint64_t mk_desc(uint32_t addr) {
    const uint64_t base = (uint64_t(2) << 61) | (uint64_t(1) << 46)
                        | (uint64_t(64) << 32) | (uint64_t(1) << 16);
    return base | ((uint64_t)(addr >> 4) & 0x3FFF);
}
#define SWZ128(b) ((b) ^ (((b) >> 3) & 0x70))
// idesc: cfmt=F32(1)<<4, a=TF32(2)<<7, b=TF32(2)<<10, N=128 ->16<<17, M=128 ->8<<24
#define TC_IDESC ((1u<<4)|(2u<<7)|(2u<<10)|(16u<<17)|(8u<<24))
#endif  // TC_OK

__device__ __forceinline__ void mma_tf32(float& c0, float& c1, float& c2, float& c3,
                                         unsigned a0, unsigned a1, unsigned a2, unsigned a3,
                                         unsigned b0, unsigned b1) {
    asm volatile(
        "mma.sync.aligned.m16n8k8.row.col.f32.tf32.tf32.f32 "
        "{%0,%1,%2,%3}, {%4,%5,%6,%7}, {%8,%9}, {%0,%1,%2,%3};"
        : "+f"(c0), "+f"(c1), "+f"(c2), "+f"(c3)
        : "r"(a0), "r"(a1), "r"(a2), "r"(a3), "r"(b0), "r"(b1));
}

// ---------------- LayerNorm: one block per row -------------------------------
__global__ __launch_bounds__(256)
void ln_kernel(const float* __restrict__ x, const float* __restrict__ w,
               const float* __restrict__ b, float* __restrict__ out) {
    const int row = blockIdx.x;
    const int tid = threadIdx.x;
    const float* xr = x + (size_t)row * D_;
    float v[3];
    float s = 0.f;
    #pragma unroll
    for (int i = 0; i < 3; i++) { v[i] = xr[tid + i*256]; s += v[i]; }

    __shared__ float red[8];
    __shared__ float bc[2];
    #pragma unroll
    for (int o = 16; o; o >>= 1) s += __shfl_xor_sync(0xffffffffu, s, o);
    if ((tid & 31) == 0) red[tid >> 5] = s;
    __syncthreads();
    if (tid == 0) {
        float t = 0.f;
        #pragma unroll
        for (int i = 0; i < 8; i++) t += red[i];
        bc[0] = t * (1.0f / D_);
    }
    __syncthreads();
    const float mu = bc[0];

    float s2 = 0.f;
    #pragma unroll
    for (int i = 0; i < 3; i++) { float d = v[i] - mu; s2 += d * d; }
    #pragma unroll
    for (int o = 16; o; o >>= 1) s2 += __shfl_xor_sync(0xffffffffu, s2, o);
    if ((tid & 31) == 0) red[tid >> 5] = s2;
    __syncthreads();
    if (tid == 0) {
        float t = 0.f;
        #pragma unroll
        for (int i = 0; i < 8; i++) t += red[i];
        bc[1] = rsqrtf(t * (1.0f / D_) + EPS_);
    }
    __syncthreads();
    const float rstd = bc[1];

    float* orow = out + (size_t)row * D_;
    #pragma unroll
    for (int i = 0; i < 3; i++) {
        int c = tid + i*256;
        orow[c] = (v[i] - mu) * rstd * w[c] + b[c];
    }
}

// ---------------- unified tf32 NT GEMM ---------------------------------------
// TC path now software-pipelined: stage s+1 global loads issue before the
// mbar wait + stores of stage s, hiding LDG latency behind MMA s-1/s.
#define STAGE_BYTES 16384
#define GEMM_DYN_SMEM (4*STAGE_BYTES + 1024)

template<int EP>
__global__ __launch_bounds__(256, 2)
void gemm_u(const float* __restrict__ A, const float* __restrict__ W,
            const float* __restrict__ bias, const float* __restrict__ res,
            float* __restrict__ C, int M, int N, int K) {
#if TC_OK
    extern __shared__ char dsm[];
    __shared__ uint32_t tmem_ptr_s[1];
    __shared__ __align__(8) uint64_t mbar_s[2];

    const int tid  = threadIdx.x;
    const int warp = tid >> 5;
    const int lane = tid & 31;
    const int m0 = blockIdx.y << 7, n0 = blockIdx.x << 7;

    uint32_t rawb = smem_u32(dsm);
    uint32_t ab   = (rawb + 1023u) & ~1023u;
    char* sbase = dsm + (ab - rawb);
    char* sA[2] = { sbase,                 sbase + STAGE_BYTES };
    char* sB[2] = { sbase + 2*STAGE_BYTES, sbase + 3*STAGE_BYTES };
    const uint32_t aAddr[2] = { ab, ab + STAGE_BYTES };
    const uint32_t bAddr[2] = { ab + 2*STAGE_BYTES, ab + 3*STAGE_BYTES };
    const uint32_t mbar0 = smem_u32(&mbar_s[0]);
    const uint32_t mbar1 = smem_u32(&mbar_s[1]);

    if (warp == 0) {
        TC_ALLOC(smem_u32(tmem_ptr_s), 128);
        TC_RELINQ();
    }
    if (tid == 0) { MBAR_INIT(mbar0, 1); MBAR_INIT(mbar1, 1); }
    __syncthreads();
    uint32_t tmem;
    asm volatile("ld.shared.b32 %0, [%1];" : "=r"(tmem) : "r"(smem_u32(tmem_ptr_s)));

    const int prow = tid >> 3;    // 0..31 (+32p)
    const int psub = tid & 7;     // 16B chunk

    // per-pass base pointers and swizzled smem offsets
    const float* Ap[4];
    const float* Wp[4];
    uint32_t soff[4];
    #pragma unroll
    for (int p = 0; p < 4; p++) {
        const int r = prow + (p << 5);
        Ap[p] = A + (size_t)(m0 + r) * K + (psub << 2);
        Wp[p] = W + (size_t)(n0 + r) * K + (psub << 2);
        soff[p] = SWZ128((r << 7) | (psub << 4));
    }

    const int nst = K >> 5;

    float4 pa[4], pw[4];
    #pragma unroll
    for (int p = 0; p < 4; p++) {
        pa[p] = *(const float4*)(Ap[p]);
        pw[p] = *(const float4*)(Wp[p]);
    }

    for (int s = 0; s < nst; s++) {
        const int b = s & 1;

        // prefetch next stage BEFORE wait/stores (overlaps MMA + wait)
        float4 na[4], nw[4];
        if (s + 1 < nst) {
            const int ko = (s + 1) << 5;
            #pragma unroll
            for (int p = 0; p < 4; p++) {
                na[p] = *(const float4*)(Ap[p] + ko);
                nw[p] = *(const float4*)(Wp[p] + ko);
            }
        }

        if (s >= 2) MBAR_WAIT(b ? mbar1 : mbar0, ((s - 2) >> 1) & 1);

        #pragma unroll
        for (int p = 0; p < 4; p++) {
            uint4 at, wt;
            at.x = f2tf32(pa[p].x); at.y = f2tf32(pa[p].y); at.z = f2tf32(pa[p].z); at.w = f2tf32(pa[p].w);
            wt.x = f2tf32(pw[p].x); wt.y = f2tf32(pw[p].y); wt.z = f2tf32(pw[p].z); wt.w = f2tf32(pw[p].w);
            *(uint4*)(sA[b] + soff[p]) = at;
            *(uint4*)(sB[b] + soff[p]) = wt;
        }
        FENCE_ASYNC_SH();
        __syncthreads();

        if (warp == 0 && elect_one()) {
            const uint64_t ad = mk_desc(aAddr[b]);
            const uint64_t bd = mk_desc(bAddr[b]);
            #pragma unroll
            for (int kk = 0; kk < 4; kk++)
                tc_mma_tf32_ss(tmem, ad + kk*2, bd + kk*2, TC_IDESC, (s > 0) || (kk > 0));
            TC_COMMIT(b ? mbar1 : mbar0);
        }
        // no trailing syncthreads: buffer-reuse safety is carried by the
        // commit-mbarrier wait (stage s+2 waits on stage s's commit).

        #pragma unroll
        for (int p = 0; p < 4; p++) { pa[p] = na[p]; pw[p] = nw[p]; }
    }

    const int ls = nst - 1;
    MBAR_WAIT((ls & 1) ? mbar1 : mbar0, (ls >> 1) & 1);
    TC_FENCE_AFTER();

    uint32_t dr[64];
    const int cb = (warp >> 2) << 6;
    TC_LD_X32(dr,      tmem + cb);
    TC_LD_X32(dr + 32, tmem + cb + 32);
    TC_WAIT_LD();

    const int r  = m0 + ((warp & 3) << 5) + lane;
    const int cg = n0 + cb;
    float* crow = C + (size_t)r * N + cg;
    const float* rrow = (EP == 3) ? (res + (size_t)r * N + cg) : nullptr;
    #pragma unroll
    for (int j4 = 0; j4 < 16; j4++) {
        float4 bv = *(const float4*)(bias + cg + (j4 << 2));
        float4 o;
        o.x = __uint_as_float(dr[j4*4+0]) + bv.x;
        o.y = __uint_as_float(dr[j4*4+1]) + bv.y;
        o.z = __uint_as_float(dr[j4*4+2]) + bv.z;
        o.w = __uint_as_float(dr[j4*4+3]) + bv.w;
        if (EP == 1) { o.x *= SCALING_; o.y *= SCALING_; o.z *= SCALING_; o.w *= SCALING_; }
        if (EP == 2) {
            o.x = 0.5f * o.x * (1.0f + erff(o.x * 0.70710678118654752f));
            o.y = 0.5f * o.y * (1.0f + erff(o.y * 0.70710678118654752f));
            o.z = 0.5f * o.z * (1.0f + erff(o.z * 0.70710678118654752f));
            o.w = 0.5f * o.w * (1.0f + erff(o.w * 0.70710678118654752f));
        }
        if (EP == 3) {
            float4 rv = *(const float4*)(rrow + (j4 << 2));
            o.x += rv.x; o.y += rv.y; o.z += rv.z; o.w += rv.w;
        }
        *(float4*)(crow + (j4 << 2)) = o;
    }

    __syncthreads();
    if (warp == 0) TC_DEALLOC(tmem, 128);

#else  // fallback: mma.sync path
    extern __shared__ char dsm[];
    typedef unsigned SmemBuf[128][16];
    SmemBuf* As = reinterpret_cast<SmemBuf*>(dsm);
    SmemBuf* Ws = reinterpret_cast<SmemBuf*>(dsm + 2 * sizeof(SmemBuf));

    const int tid  = threadIdx.x;
    const int lane = tid & 31;
    const int warp = tid >> 5;
    const int wm = (warp >> 2) * 64;
    const int wn = (warp & 3) * 32;
    const int grp = lane >> 2;
    const int qk  = lane & 3;

    const int m0 = blockIdx.y << 7, n0 = blockIdx.x << 7;

    const int ldr = tid >> 2;
    const int sub = tid & 3;
    const float* Ap0 = A + (size_t)(m0 + ldr) * K + (sub << 2);
    const float* Ap1 = A + (size_t)(m0 + ldr + 64) * K + (sub << 2);
    const float* Wp0 = W + (size_t)(n0 + ldr) * K + (sub << 2);
    const float* Wp1 = W + (size_t)(n0 + ldr + 64) * K + (sub << 2);
    const int sw0 = ((ldr >> 1) & 3);
    const int sw1 = (((ldr + 64) >> 1) & 3);

    float acc[4][4][4];
    #pragma unroll
    for (int i = 0; i < 4; i++)
        #pragma unroll
        for (int j = 0; j < 4; j++)
            #pragma unroll
            for (int f = 0; f < 4; f++) acc[i][j][f] = 0.f;

    const int ntiles = K >> 4;

    #define STORE_TILE(buf, a0v, a1v, w0v, w1v)                                              \
        do {                                                                                  \
            As[buf][ldr   ][((0^sw0)<<2)+sub]=f2tf32(a0v.x); As[buf][ldr   ][((1^sw0)<<2)+sub]=f2tf32(a0v.y); \
            As[buf][ldr   ][((2^sw0)<<2)+sub]=f2tf32(a0v.z); As[buf][ldr   ][((3^sw0)<<2)+sub]=f2tf32(a0v.w); \
            As[buf][ldr+64][((0^sw1)<<2)+sub]=f2tf32(a1v.x); As[buf][ldr+64][((1^sw1)<<2)+sub]=f2tf32(a1v.y); \
            As[buf][ldr+64][((2^sw1)<<2)+sub]=f2tf32(a1v.z); As[buf][ldr+64][((3^sw1)<<2)+sub]=f2tf32(a1v.w); \
            Ws[buf][ldr   ][((0^sw0)<<2)+sub]=f2tf32(w0v.x); Ws[buf][ldr   ][((1^sw0)<<2)+sub]=f2tf32(w0v.y); \
            Ws[buf][ldr   ][((2^sw0)<<2)+sub]=f2tf32(w0v.z); Ws[buf][ldr   ][((3^sw0)<<2)+sub]=f2tf32(w0v.w); \
            Ws[buf][ldr+64][((0^sw1)<<2)+sub]=f2tf32(w1v.x); Ws[buf][ldr+64][((1^sw1)<<2)+sub]=f2tf32(w1v.y); \
            Ws[buf][ldr+64][((2^sw1)<<2)+sub]=f2tf32(w1v.z); Ws[buf][ldr+64][((3^sw1)<<2)+sub]=f2tf32(w1v.w); \
        } while (0)

    {
        float4 a0 = *(const float4*)(Ap0);
        float4 a1 = *(const float4*)(Ap1);
        float4 w0 = *(const float4*)(Wp0);
        float4 w1 = *(const float4*)(Wp1);
        STORE_TILE(0, a0, a1, w0, w1);
    }
    __syncthreads();

    for (int it = 0; it < ntiles; it++) {
        const int cur = it & 1, nxt = cur ^ 1;
        float4 a0, a1, w0, w1;
        const bool have_next = (it + 1) < ntiles;
        if (have_next) {
            const int ko = (it + 1) << 4;
            a0 = *(const float4*)(Ap0 + ko);
            a1 = *(const float4*)(Ap1 + ko);
            w0 = *(const float4*)(Wp0 + ko);
            w1 = *(const float4*)(Wp1 + ko);
        }

        uint4 Bv[4];
        #pragma unroll
        for (int ni = 0; ni < 4; ni++) {
            const int rn = wn + (ni << 3) + grp;
            Bv[ni] = *(const uint4*)&Ws[cur][rn][((qk ^ ((rn >> 1) & 3)) << 2)];
        }
        #pragma unroll
        for (int mi = 0; mi < 4; mi++) {
            const int rl = wm + (mi << 4) + grp;
            const int rh = rl + 8;
            const uint4 Alo = *(const uint4*)&As[cur][rl][((qk ^ ((rl >> 1) & 3)) << 2)];
            const uint4 Ahi = *(const uint4*)&As[cur][rh][((qk ^ ((rh >> 1) & 3)) << 2)];
            #pragma unroll
            for (int ni = 0; ni < 4; ni++) {
                mma_tf32(acc[mi][ni][0], acc[mi][ni][1], acc[mi][ni][2], acc[mi][ni][3],
                         Alo.x, Ahi.x, Alo.y, Ahi.y, Bv[ni].x, Bv[ni].y);
                mma_tf32(acc[mi][ni][0], acc[mi][ni][1], acc[mi][ni][2], acc[mi][ni][3],
                         Alo.z, Ahi.z, Alo.w, Ahi.w, Bv[ni].z, Bv[ni].w);
            }
        }

        if (have_next) {
            STORE_TILE(nxt, a0, a1, w0, w1);
        }
        __syncthreads();
    }
    #undef STORE_TILE

    #pragma unroll
    for (int mi = 0; mi < 4; mi++) {
        #pragma unroll
        for (int ni = 0; ni < 4; ni++) {
            #pragma unroll
            for (int f = 0; f < 4; f++) {
                const int r = m0 + wm + (mi << 4) + grp + ((f >> 1) << 3);
                const int c = n0 + wn + (ni << 3) + (qk << 1) + (f & 1);
                float val = acc[mi][ni][f] + bias[c];
                if (EP == 1) val *= SCALING_;
                if (EP == 2) val = 0.5f * val * (1.0f + erff(val * 0.70710678118654752f));
                if (EP == 3) val += res[(size_t)r * N + c];
                C[(size_t)r * N + c] = val;
            }
        }
    }
#endif
}

// ---------------- RoPE (interleaved pairs), in-place -------------------------
__global__ void rope_kernel(float* __restrict__ t, const float* __restrict__ freqs, int npairs) {
    int idx = blockIdx.x * blockDim.x + threadIdx.x;
    if (idx >= npairs) return;
    const int row = idx / (D_ / 2);
    const int p   = idx - row * (D_ / 2);
    const int i   = p & 31;
    const int n   = row & (N_ - 1);
    const float ang = (float)n * freqs[i];
    const float c = cosf(ang), s = sinf(ang);
    float* base = t + (size_t)row * D_ + p * 2;
    const float x0 = base[0], x1 = base[1];
    base[0] = x0 * c - x1 * s;
    base[1] = x1 * c + x0 * s;
}

// ---------------- flash attention, tf32 mma.sync, BQ=128 BK=64 ---------------
#define ATTN_SMEM (16384 + 16384 + 32768 + 64)
__global__ __launch_bounds__(256, 2)
void attn_tc(const float* __restrict__ q, const float* __restrict__ k,
             const float* __restrict__ v, const unsigned char* __restrict__ pm,
             float* __restrict__ out) {
    extern __shared__ char asmem[];
    unsigned* Ks = (unsigned*)asmem;               // [4][64][16]  keys x d
    unsigned* Vt = (unsigned*)(asmem + 16384);     // [4][64][16]  dims x keys
    unsigned* Ps = (unsigned*)(asmem + 32768);     // [4][128][16] qrows x keys
    unsigned char* Ms = (unsigned char*)(asmem + 65536);

    const int tid = threadIdx.x, warp = tid >> 5, lane = tid & 31;
    const int grp = lane >> 2, qk = lane & 3;
    const int qt = blockIdx.x, bh = blockIdx.y;
    const int b = bh / H_, h = bh - b * H_;
    const int row0 = b * N_ + qt * 128;
    const int colh = h * HD_;
    const int wr = warp << 4;
    const int rl0 = wr + grp;
    const int rl1 = rl0 + 8;
    const int r0 = row0 + rl0;

    unsigned aq[8][4];
    {
        const float* q0 = q + (size_t)r0 * D_ + colh;
        const float* q1 = q0 + (size_t)8 * D_;
        #pragma unroll
        for (int s = 0; s < 8; s++) {
            aq[s][0] = f2tf32(q0[s*8 + qk]);
            aq[s][1] = f2tf32(q1[s*8 + qk]);
            aq[s][2] = f2tf32(q0[s*8 + qk + 4]);
            aq[s][3] = f2tf32(q1[s*8 + qk + 4]);
        }
    }

    float o_[8][4];
    #pragma unroll
    for (int nt = 0; nt < 8; nt++) { o_[nt][0]=0.f; o_[nt][1]=0.f; o_[nt][2]=0.f; o_[nt][3]=0.f; }
    float m0 = -3.0e38f, m1 = -3.0e38f, l0 = 0.f, l1 = 0.f;

    const int lkey = tid >> 2, lq = tid & 3;
    const int swk = (lkey >> 1) & 3;
    const int vpl = lkey >> 4, vkk = lkey & 15;
    const int swp0 = (rl0 >> 1) & 3, swp1 = (rl1 >> 1) & 3;

    for (int kt = 0; kt < N_; kt += 64) {
        __syncthreads();
        {
            const size_t gbase = (size_t)(b * N_ + kt + lkey) * D_ + colh;
            #pragma unroll
            for (int c = 0; c < 4; c++) {
                const float4 k4 = *(const float4*)(k + gbase + 16*c + 4*lq);
                const float4 v4 = *(const float4*)(v + gbase + 16*c + 4*lq);
                unsigned* kp = Ks + (c << 10) + (lkey << 4);
                kp[((0^swk)<<2)+lq] = f2tf32(k4.x);
                kp[((1^swk)<<2)+lq] = f2tf32(k4.y);
                kp[((2^swk)<<2)+lq] = f2tf32(k4.z);
                kp[((3^swk)<<2)+lq] = f2tf32(k4.w);
                const float vv[4] = {v4.x, v4.y, v4.z, v4.w};
                #pragma unroll
                for (int i = 0; i < 4; i++) {
                    const int d = 16*c + 4*lq + i;
                    const int quad = (vkk & 3) ^ ((d >> 1) & 3);
                    Vt[(vpl << 10) + (d << 4) + (quad << 2) + (vkk >> 2)] = f2tf32(vv[i]);
                }
            }
            if (tid < 64) Ms[tid] = pm[b * N_ + kt + tid];
        }
        __syncthreads();

        float s_[8][4];
        #pragma unroll
        for (int nt = 0; nt < 8; nt++) { s_[nt][0]=0.f; s_[nt][1]=0.f; s_[nt][2]=0.f; s_[nt][3]=0.f; }
        #pragma unroll
        for (int c = 0; c < 4; c++) {
            #pragma unroll
            for (int nt = 0; nt < 8; nt++) {
                const int rn = (nt << 3) + grp;
                const uint4 Bv = *(const uint4*)(Ks + (c << 10) + (rn << 4)
                                                 + ((qk ^ ((rn >> 1) & 3)) << 2));
                mma_tf32(s_[nt][0], s_[nt][1], s_[nt][2], s_[nt][3],
                         aq[2*c][0], aq[2*c][1], aq[2*c][2], aq[2*c][3], Bv.x, Bv.y);
                mma_tf32(s_[nt][0], s_[nt][1], s_[nt][2], s_[nt][3],
                         aq[2*c+1][0], aq[2*c+1][1], aq[2*c+1][2], aq[2*c+1][3], Bv.z, Bv.w);
            }
        }

        float mx0 = -3.0e38f, mx1 = -3.0e38f;
        #pragma unroll
        for (int nt = 0; nt < 8; nt++) {
            const int c0 = (nt << 3) + (qk << 1);
            const bool k0m = Ms[c0] != 0, k1m = Ms[c0 + 1] != 0;
            s_[nt][0] = k0m ? -3.0e38f : s_[nt][0] * 0.125f;
            s_[nt][1] = k1m ? -3.0e38f : s_[nt][1] * 0.125f;
            s_[nt][2] = k0m ? -3.0e38f : s_[nt][2] * 0.125f;
            s_[nt][3] = k1m ? -3.0e38f : s_[nt][3] * 0.125f;
            mx0 = fmaxf(mx0, fmaxf(s_[nt][0], s_[nt][1]));
            mx1 = fmaxf(mx1, fmaxf(s_[nt][2], s_[nt][3]));
        }
        mx0 = fmaxf(mx0, __shfl_xor_sync(0xffffffffu, mx0, 1));
        mx0 = fmaxf(mx0, __shfl_xor_sync(0xffffffffu, mx0, 2));
        mx1 = fmaxf(mx1, __shfl_xor_sync(0xffffffffu, mx1, 1));
        mx1 = fmaxf(mx1, __shfl_xor_sync(0xffffffffu, mx1, 2));

        const float mn0 = fmaxf(m0, mx0), mn1 = fmaxf(m1, mx1);
        const float al0 = __expf(m0 - mn0), al1 = __expf(m1 - mn1);
        m0 = mn0; m1 = mn1;
        float rs0 = 0.f, rs1 = 0.f;
        #pragma unroll
        for (int nt = 0; nt < 8; nt++) {
            s_[nt][0] = __expf(s_[nt][0] - mn0);
            s_[nt][1] = __expf(s_[nt][1] - mn0);
            s_[nt][2] = __expf(s_[nt][2] - mn1);
            s_[nt][3] = __expf(s_[nt][3] - mn1);
            rs0 += s_[nt][0] + s_[nt][1];
            rs1 += s_[nt][2] + s_[nt][3];
            o_[nt][0] *= al0; o_[nt][1] *= al0;
            o_[nt][2] *= al1; o_[nt][3] *= al1;
        }
        rs0 += __shfl_xor_sync(0xffffffffu, rs0, 1);
        rs0 += __shfl_xor_sync(0xffffffffu, rs0, 2);
        rs1 += __shfl_xor_sync(0xffffffffu, rs1, 1);
        rs1 += __shfl_xor_sync(0xffffffffu, rs1, 2);
        l0 = l0 * al0 + rs0;
        l1 = l1 * al1 + rs1;

        #pragma unroll
        for (int nt = 0; nt < 8; nt++) {
            #pragma unroll
            for (int i2 = 0; i2 < 2; i2++) {
                const int ck = (nt << 3) + (qk << 1) + i2;
                const int pl = ck >> 4, kk = ck & 15;
                const int w_ = kk >> 2;
                Ps[(pl << 11) + (rl0 << 4) + ((((kk & 3) ^ swp0)) << 2) + w_] = f2tf32(s_[nt][i2]);
                Ps[(pl << 11) + (rl1 << 4) + ((((kk & 3) ^ swp1)) << 2) + w_] = f2tf32(s_[nt][2 + i2]);
            }
        }
        __syncthreads();

        #pragma unroll
        for (int c = 0; c < 4; c++) {
            const uint4 Alo = *(const uint4*)(Ps + (c << 11) + (rl0 << 4) + ((qk ^ swp0) << 2));
            const uint4 Ahi = *(const uint4*)(Ps + (c << 11) + (rl1 << 4) + ((qk ^ swp1) << 2));
            #pragma unroll
            for (int nt = 0; nt < 8; nt++) {
                const int rn = (nt << 3) + grp;
                const uint4 Bv = *(const uint4*)(Vt + (c << 10) + (rn << 4)
                                                 + ((qk ^ ((rn >> 1) & 3)) << 2));
                mma_tf32(o_[nt][0], o_[nt][1], o_[nt][2], o_[nt][3],
                         Alo.x, Ahi.x, Alo.y, Ahi.y, Bv.x, Bv.y);
                mma_tf32(o_[nt][0], o_[nt][1], o_[nt][2], o_[nt][3],
                         Alo.z, Ahi.z, Alo.w, Ahi.w, Bv.z, Bv.w);
            }
        }
    }

    const float inv0 = 1.0f / l0, inv1 = 1.0f / l1;
    float* out0 = out + (size_t)r0 * D_ + colh;
    float* out1 = out0 + (size_t)8 * D_;
    #pragma unroll
    for (int nt = 0; nt < 8; nt++) {
        const int c0 = (nt << 3) + (qk << 1);
        out0[c0]     = o_[nt][0] * inv0;
        out0[c0 + 1] = o_[nt][1] * inv0;
        out1[c0]     = o_[nt][2] * inv1;
        out1[c0 + 1] = o_[nt][3] * inv1;
    }
}

// ---------------- launch ------------------------------------------------------
extern "C" void kernel_launch(void* const* d_in, const int* in_sizes, int n_in,
                              void* d_out, int out_size) {
    const float* x     = (const float*)d_in[0];
    const unsigned char* pmask = (const unsigned char*)d_in[1];
    const float* wq = (const float*)d_in[2];
    const float* bq = (const float*)d_in[3];
    const float* wk = (const float*)d_in[4];
    const float* bk = (const float*)d_in[5];
    const float* wv = (const float*)d_in[6];
    const float* bv = (const float*)d_in[7];
    const float* wo = (const float*)d_in[8];
    const float* bo = (const float*)d_in[9];
    const float* w1 = (const float*)d_in[10];
    const float* b1 = (const float*)d_in[11];
    const float* w2 = (const float*)d_in[12];
    const float* b2 = (const float*)d_in[13];
    const float* ln1w = (const float*)d_in[14];
    const float* ln1b = (const float*)d_in[15];
    const float* ln2w = (const float*)d_in[16];
    const float* ln2b = (const float*)d_in[17];
    const float* freqs = (const float*)d_in[18];
    float* out = (float*)d_out;

    float *ph, *pq, *pk, *pv, *patt, *pff;
    cudaGetSymbolAddress((void**)&ph,   g_h);
    cudaGetSymbolAddress((void**)&pq,   g_q);
    cudaGetSymbolAddress((void**)&pk,   g_k);
    cudaGetSymbolAddress((void**)&pv,   g_v);
    cudaGetSymbolAddress((void**)&patt, g_att);
    cudaGetSymbolAddress((void**)&pff,  g_ff);

    cudaFuncSetAttribute(gemm_u<0>, cudaFuncAttributeMaxDynamicSharedMemorySize, GEMM_DYN_SMEM);
    cudaFuncSetAttribute(gemm_u<1>, cudaFuncAttributeMaxDynamicSharedMemorySize, GEMM_DYN_SMEM);
    cudaFuncSetAttribute(gemm_u<2>, cudaFuncAttributeMaxDynamicSharedMemorySize, GEMM_DYN_SMEM);
    cudaFuncSetAttribute(gemm_u<3>, cudaFuncAttributeMaxDynamicSharedMemorySize, GEMM_DYN_SMEM);
    cudaFuncSetAttribute(attn_tc,   cudaFuncAttributeMaxDynamicSharedMemorySize, ATTN_SMEM);

    const dim3 gD(D_ / 128, M_ / 128);     // (6, 64)
    const dim3 gF(FF_ / 128, M_ / 128);    // (24, 64)

    // LN1
    ln_kernel<<<M_, 256>>>(x, ln1w, ln1b, ph);
    // QKV projections
    gemm_u<1><<<gD, 256, GEMM_DYN_SMEM>>>(ph, wq, bq, nullptr, pq, M_, D_, D_);
    gemm_u<0><<<gD, 256, GEMM_DYN_SMEM>>>(ph, wk, bk, nullptr, pk, M_, D_, D_);
    gemm_u<0><<<gD, 256, GEMM_DYN_SMEM>>>(ph, wv, bv, nullptr, pv, M_, D_, D_);
    // RoPE on q and k
    const int npairs = M_ * (D_ / 2);
    rope_kernel<<<(npairs + 255) / 256, 256>>>(pq, freqs, npairs);
    rope_kernel<<<(npairs + 255) / 256, 256>>>(pk, freqs, npairs);
    // attention (tf32 tensor cores)
    attn_tc<<<dim3(N_ / 128, B_ * H_), 256, ATTN_SMEM>>>(pq, pk, pv, pmask, patt);
    // O projection + residual (x) -> d_out
    gemm_u<3><<<gD, 256, GEMM_DYN_SMEM>>>(patt, wo, bo, x, out, M_, D_, D_);
    // LN2 (reuse g_h)
    ln_kernel<<<M_, 256>>>(out, ln2w, ln2b, ph);
    // FFN1 with exact GELU
    gemm_u<2><<<gF, 256, GEMM_DYN_SMEM>>>(ph, w1, b1, nullptr, pff, M_, FF_, D_);
    // FFN2 + residual (d_out) -> d_out
    gemm_u<3><<<gD, 256, GEMM_DYN_SMEM>>>(pff, w2, b2, out, out, M_, D_, FF_);
}